// round 15
// baseline (speedup 1.0000x reference)
#include <cuda_runtime.h>
#include <cuda_fp16.h>
#include <math.h>
#include <stdint.h>

// Problem config
#define E_   1024
#define H_   16
#define D_   64
#define L_   6
#define FF_  4096
#define B_   4
#define T_   1024
#define BT_  4096
#define V_   32000
#define QKVW 3072
#define NVB  (V_ / 128)      // 250 head col-blocks

// Activation scratch
__device__ __align__(16) float    g_x[BT_ * E_];
__device__ __align__(16) uint32_t g_h[BT_ * E_ / 2];
__device__ __align__(16) uint32_t g_qk[BT_ * 1024];
__device__ __align__(16) uint32_t g_vt[B_ * H_ * 64 * T_ / 2];
__device__ __align__(16) uint32_t g_oc[BT_ * E_ / 2];
__device__ __align__(16) uint32_t g_ff[BT_ * FF_ / 2];
__device__ __align__(16) float2   g_part[(size_t)BT_ * NVB];   // per-(row,colblk) (max, sumexp)
__device__ __align__(16) float    g_rl[BT_];

// Fragment-packed fp16 weights (tile = 64k x 128n = 4096 b32 words)
__device__ __align__(16) uint32_t g_wqkv[(size_t)L_ * E_ * QKVW / 2];
__device__ __align__(16) uint32_t g_wp[(size_t)L_ * E_ * E_ / 2];
__device__ __align__(16) uint32_t g_w1[(size_t)L_ * E_ * FF_ / 2];
__device__ __align__(16) uint32_t g_w2[(size_t)L_ * FF_ * E_ / 2];
__device__ __align__(16) uint32_t g_wh[(size_t)E_ * V_ / 2];

__device__ __forceinline__ uint32_t h2(float a, float b) {
    __half2 t = __floats2half2_rn(a, b);
    return *(uint32_t*)&t;
}
__device__ __forceinline__ uint32_t hscale(uint32_t u, __half2 s) {
    __half2 t = __hmul2(*(__half2*)&u, s);
    return *(uint32_t*)&t;
}

__device__ __forceinline__ void cpa16(void* s, const void* g) {
    uint32_t sa = (uint32_t)__cvta_generic_to_shared(s);
    asm volatile("cp.async.cg.shared.global [%0], [%1], 16;\n" :: "r"(sa), "l"(g));
}
__device__ __forceinline__ void cpa_commit() { asm volatile("cp.async.commit_group;\n"); }
template<int N> __device__ __forceinline__ void cpa_wait() {
    asm volatile("cp.async.wait_group %0;\n" :: "n"(N));
}

#define MMA_F16(d0,d1,d2,d3,a0,a1,a2,a3,b0,b1) \
    asm volatile("mma.sync.aligned.m16n8k16.row.col.f32.f16.f16.f32 " \
        "{%0,%1,%2,%3}, {%4,%5,%6,%7}, {%8,%9}, {%0,%1,%2,%3};\n" \
        : "+f"(d0), "+f"(d1), "+f"(d2), "+f"(d3) \
        : "r"(a0), "r"(a1), "r"(a2), "r"(a3), "r"(b0), "r"(b1))

// ---------------------------------------------------------------------------
// fp16 GEMM: 128x128 CTA tile, BK=64, 3-stage cp.async (single barrier/iter).
// OMODE 0: fp32 row-major out (+bias/resid/relu)
// OMODE 1: packed-A fp16 out (+bias, relu)
// OMODE 2: qkv split out (Q/K -> Cw rows, V -> (half*)Cf transposed)
// OMODE 3: head: fp32 logits out (+bias) AND per-row partial (max, sumexp)
// ---------------------------------------------------------------------------
#define TSZ 4096
#define G_SMEM (3 * 2 * TSZ * 4)

template<int OMODE>
__global__ __launch_bounds__(256, 2)
void mma_gemm(const uint32_t* __restrict__ Ap,
              const uint32_t* __restrict__ Bp,
              float* __restrict__ Cf,
              uint32_t* __restrict__ Cw,
              float2* __restrict__ part,
              int ldc, int M, int N, int K,
              const float* __restrict__ bias,
              const float* __restrict__ resid,
              int relu)
{
    extern __shared__ __align__(16) uint32_t dsm[];
    uint32_t* Abuf = dsm;
    uint32_t* Bbuf = dsm + 3 * TSZ;

    const int row0 = blockIdx.y * 128;
    const int col0 = blockIdx.x * 128;
    const int tid  = threadIdx.x;
    const int warp = tid >> 5;
    const int lane = tid & 31;
    const int wm   = (warp >> 2) * 64;
    const int wm16 = (warp >> 2) * 4;
    const int wn8  = (warp & 3) * 4;
    const int qr   = lane >> 2;
    const int qc   = lane & 3;

    const int ntn = N >> 7;
    const int nkt = K >> 6;
    const int mt  = row0 >> 7;

    float acc[4][4][4];
#pragma unroll
    for (int i = 0; i < 4; i++)
#pragma unroll
        for (int j = 0; j < 4; j++)
#pragma unroll
            for (int t = 0; t < 4; t++) acc[i][j][t] = 0.f;

    auto issue = [&](int it) {
        int buf = it % 3;
        uint32_t* as = Abuf + buf * TSZ;
        const uint32_t* at = Ap + ((long long)mt * nkt + it) * TSZ;
#pragma unroll
        for (int i = 0; i < 4; i++) {
            int e = tid + i * 256;
            cpa16(&as[e * 4], at + e * 4);
        }
        uint32_t* bs = Bbuf + buf * TSZ;
        const uint32_t* bt = Bp + ((long long)it * ntn + (col0 >> 7)) * TSZ;
#pragma unroll
        for (int i = 0; i < 4; i++) {
            int e = tid + i * 256;
            cpa16(&bs[e * 4], bt + e * 4);
        }
        cpa_commit();
    };

    issue(0);
    issue(1);

    for (int it = 0; it < nkt; it++) {
        if (it + 1 < nkt) cpa_wait<1>();
        else              cpa_wait<0>();
        __syncthreads();
        if (it + 2 < nkt) issue(it + 2);

        const uint32_t* as = Abuf + (it % 3) * TSZ;
        const uint32_t* bs = Bbuf + (it % 3) * TSZ;

#pragma unroll
        for (int kt = 0; kt < 4; kt++) {
            uint4 a[4];
#pragma unroll
            for (int mi = 0; mi < 4; mi++)
                a[mi] = *(const uint4*)&as[((wm16 + mi) * 4 + kt) * 128 + lane * 4];
            uint32_t b[4][2];
#pragma unroll
            for (int ni = 0; ni < 4; ni++) {
                uint2 t2 = *(const uint2*)&bs[((wn8 + ni) * 4 + kt) * 64 + lane * 2];
                b[ni][0] = t2.x; b[ni][1] = t2.y;
            }
#pragma unroll
            for (int mi = 0; mi < 4; mi++)
#pragma unroll
                for (int ni = 0; ni < 4; ni++)
                    MMA_F16(acc[mi][ni][0], acc[mi][ni][1], acc[mi][ni][2], acc[mi][ni][3],
                            a[mi].x, a[mi].y, a[mi].z, a[mi].w,
                            b[ni][0], b[ni][1]);
        }
    }

    if (OMODE == 0) {
#pragma unroll
        for (int mi = 0; mi < 4; mi++) {
#pragma unroll
            for (int ni = 0; ni < 4; ni++) {
#pragma unroll
                for (int half = 0; half < 2; half++) {
                    int r = row0 + wm + mi * 16 + qr + half * 8;
                    int c = col0 + (warp & 3) * 32 + ni * 8 + qc * 2;
                    float v0 = acc[mi][ni][half * 2];
                    float v1 = acc[mi][ni][half * 2 + 1];
                    if (bias) { v0 += bias[c]; v1 += bias[c + 1]; }
                    if (resid) {
                        float2 rr = *(const float2*)(resid + (long long)r * ldc + c);
                        v0 += rr.x; v1 += rr.y;
                    }
                    if (relu) { v0 = fmaxf(v0, 0.f); v1 = fmaxf(v1, 0.f); }
                    *(float2*)(Cf + (long long)r * ldc + c) = make_float2(v0, v1);
                }
            }
        }
    } else if (OMODE == 1) {
        float* stg = (float*)dsm;   // 128 x 130
        __syncthreads();
#pragma unroll
        for (int mi = 0; mi < 4; mi++)
#pragma unroll
            for (int ni = 0; ni < 4; ni++)
#pragma unroll
                for (int half = 0; half < 2; half++) {
                    int r = wm + mi * 16 + qr + half * 8;
                    int c = (warp & 3) * 32 + ni * 8 + qc * 2;
                    *(float2*)&stg[r * 130 + c] =
                        make_float2(acc[mi][ni][half * 2], acc[mi][ni][half * 2 + 1]);
                }
        __syncthreads();
        const int nktC = N >> 6;
#pragma unroll
        for (int i = 0; i < 32; i++) {
            int g  = tid + i * 256;
            int tl = g >> 12;
            int W  = g & 4095;
            int chunk = W >> 9;
            int kt = (W >> 7) & 3;
            int ln = (W >> 2) & 31;
            int w  = W & 3;
            int m  = chunk * 16 + (ln >> 2) + (w & 1) * 8;
            int k  = kt * 16 + (w >> 1) * 8 + (ln & 3) * 2;
            int c  = tl * 64 + k;
            float v0 = stg[m * 130 + c]     + bias[col0 + c];
            float v1 = stg[m * 130 + c + 1] + bias[col0 + c + 1];
            v0 = fmaxf(v0, 0.f); v1 = fmaxf(v1, 0.f);
            Cw[((long long)mt * nktC + (col0 >> 6) + tl) * 4096 + W] = h2(v0, v1);
        }
    } else if (OMODE == 2) {
        __half* vh = (__half*)Cf;
#pragma unroll
        for (int mi = 0; mi < 4; mi++) {
#pragma unroll
            for (int ni = 0; ni < 4; ni++) {
#pragma unroll
                for (int half = 0; half < 2; half++) {
                    int r = row0 + wm + mi * 16 + qr + half * 8;
                    int c = col0 + (warp & 3) * 32 + ni * 8 + qc * 2;
                    float v0 = acc[mi][ni][half * 2];
                    float v1 = acc[mi][ni][half * 2 + 1];
                    int hh = c / 192;
                    int rem = c - hh * 192;
                    int sel = rem >> 6;
                    int d = rem & 63;
                    if (sel < 2) {
                        Cw[(long long)r * 1024 + hh * 64 + sel * 32 + (d >> 1)] = h2(v0, v1);
                    } else {
                        int bb = r >> 10, t = r & 1023;
                        long long base = (long long)((bb * 16 + hh) * 64 + d) * 1024 + t;
                        vh[base]        = __float2half_rn(v0);
                        vh[base + 1024] = __float2half_rn(v1);
                    }
                }
            }
        }
    } else {
        // OMODE 3: head logits + per-row partial softmax stats over 128 cols
        // bias into acc, store logits
#pragma unroll
        for (int mi = 0; mi < 4; mi++) {
#pragma unroll
            for (int ni = 0; ni < 4; ni++) {
#pragma unroll
                for (int t = 0; t < 4; t++) {
                    int c = col0 + (warp & 3) * 32 + ni * 8 + qc * 2 + (t & 1);
                    acc[mi][ni][t] += bias[c];
                }
#pragma unroll
                for (int half = 0; half < 2; half++) {
                    int r = row0 + wm + mi * 16 + qr + half * 8;
                    int c = col0 + (warp & 3) * 32 + ni * 8 + qc * 2;
                    *(float2*)(Cf + (long long)r * ldc + c) =
                        make_float2(acc[mi][ni][half * 2], acc[mi][ni][half * 2 + 1]);
                }
            }
        }
        // partial (max, sumexp): 8 row-groups per thread
        float2* sm2 = (float2*)dsm;      // [128][4]
        __syncthreads();
#pragma unroll
        for (int g = 0; g < 8; g++) {
            int mi = g >> 1, half = g & 1;
            float m_t = -1e30f;
#pragma unroll
            for (int ni = 0; ni < 4; ni++) {
                m_t = fmaxf(m_t, acc[mi][ni][half * 2]);
                m_t = fmaxf(m_t, acc[mi][ni][half * 2 + 1]);
            }
            m_t = fmaxf(m_t, __shfl_xor_sync(0xffffffff, m_t, 1));
            m_t = fmaxf(m_t, __shfl_xor_sync(0xffffffff, m_t, 2));
            float s_t = 0.f;
#pragma unroll
            for (int ni = 0; ni < 4; ni++) {
                s_t += __expf(acc[mi][ni][half * 2]     - m_t);
                s_t += __expf(acc[mi][ni][half * 2 + 1] - m_t);
            }
            s_t += __shfl_xor_sync(0xffffffff, s_t, 1);
            s_t += __shfl_xor_sync(0xffffffff, s_t, 2);
            if (qc == 0) {
                int r = wm + mi * 16 + qr + half * 8;
                sm2[r * 4 + (warp & 3)] = make_float2(m_t, s_t);
            }
        }
        __syncthreads();
        if (tid < 128) {
            float2 p0 = sm2[tid * 4], p1 = sm2[tid * 4 + 1];
            float2 p2 = sm2[tid * 4 + 2], p3 = sm2[tid * 4 + 3];
            float M2 = fmaxf(fmaxf(p0.x, p1.x), fmaxf(p2.x, p3.x));
            float S2 = p0.y * __expf(p0.x - M2) + p1.y * __expf(p1.x - M2)
                     + p2.y * __expf(p2.x - M2) + p3.y * __expf(p3.x - M2);
            part[(long long)(row0 + tid) * ntn + (col0 >> 7)] = make_float2(M2, S2);
        }
    }
}

// ---------------------------------------------------------------------------
// Weight packing: [K,N] fp32 -> fp16 fragment tiles (64k x 128n).
// ---------------------------------------------------------------------------
__global__ __launch_bounds__(256)
void pack_w_kernel(const float* __restrict__ src, uint32_t* __restrict__ dst,
                   int N, int K)
{
    const int nt = blockIdx.x, kc = blockIdx.y, l = blockIdx.z;
    src += (long long)l * K * N;
    dst += (long long)l * K * N / 2;
    __shared__ float sm[64][129];
    const int tid = threadIdx.x;
#pragma unroll
    for (int i = 0; i < 8; i++) {
        int e = tid + i * 256;
        int r = e >> 5, c4 = e & 31;
        float4 f = *(const float4*)(src + (long long)(kc * 64 + r) * N + nt * 128 + c4 * 4);
        sm[r][c4 * 4 + 0] = f.x; sm[r][c4 * 4 + 1] = f.y;
        sm[r][c4 * 4 + 2] = f.z; sm[r][c4 * 4 + 3] = f.w;
    }
    __syncthreads();
    uint32_t* o = dst + ((long long)kc * (N >> 7) + nt) * 4096;
#pragma unroll
    for (int i = 0; i < 16; i++) {
        int W = tid + i * 256;
        int ns = W >> 8;
        int kt = (W >> 6) & 3;
        int rem = W & 63;
        int ln = rem >> 1, w = rem & 1;
        int n = ns * 8 + (ln >> 2);
        int k = kt * 16 + w * 8 + (ln & 3) * 2;
        o[W] = h2(sm[k][n], sm[k + 1][n]);
    }
}

__global__ __launch_bounds__(256)
void pack_qkv_kernel(const float* __restrict__ Wq,
                     const float* __restrict__ Wk,
                     const float* __restrict__ Wv,
                     uint32_t* __restrict__ dst)
{
    const int nt = blockIdx.x, kc = blockIdx.y, l = blockIdx.z;
    __shared__ float sm[64][129];
    const int tid = threadIdx.x;
#pragma unroll
    for (int i = 0; i < 8; i++) {
        int e = tid + i * 256;
        int r = e >> 5, c4 = e & 31;
        int n = nt * 128 + c4 * 4;
        int h = n / 192;
        int rem = n - h * 192;
        int sel = rem >> 6;
        int d = rem & 63;
        const float* W = (sel == 0) ? Wq : (sel == 1) ? Wk : Wv;
        float4 f = *(const float4*)(W + (((long long)l * H_ + h) * E_ + kc * 64 + r) * D_ + d);
        sm[r][c4 * 4 + 0] = f.x; sm[r][c4 * 4 + 1] = f.y;
        sm[r][c4 * 4 + 2] = f.z; sm[r][c4 * 4 + 3] = f.w;
    }
    __syncthreads();
    uint32_t* o = dst + (long long)l * E_ * QKVW / 2
                + ((long long)kc * (QKVW >> 7) + nt) * 4096;
#pragma unroll
    for (int i = 0; i < 16; i++) {
        int W = tid + i * 256;
        int ns = W >> 8;
        int kt = (W >> 6) & 3;
        int rem = W & 63;
        int ln = rem >> 1, w = rem & 1;
        int n = ns * 8 + (ln >> 2);
        int k = kt * 16 + w * 8 + (ln & 3) * 2;
        o[W] = h2(sm[k][n], sm[k + 1][n]);
    }
}

// ---------------------------------------------------------------------------
// Fused causal flash attention, fp16 mma (unchanged from R14).
// ---------------------------------------------------------------------------
#define KVW 36
#define KVSZ (64 * KVW)
#define FL_SMEM ((4 * KVSZ + 4096) * 4)

__global__ __launch_bounds__(256, 2)
void flash_kernel(const uint32_t* __restrict__ qk,
                  const uint32_t* __restrict__ vtw,
                  uint32_t* __restrict__ oc)
{
    extern __shared__ __align__(16) uint32_t fsm[];
    uint32_t* Kb = fsm;
    uint32_t* Vb = fsm + 2 * KVSZ;
    uint32_t* Ps = fsm + 4 * KVSZ;

    const int row0 = blockIdx.x * 128;
    const int b    = blockIdx.y >> 4;
    const int h    = blockIdx.y & 15;
    const int tid  = threadIdx.x;
    const int wid  = tid >> 5;
    const int lane = tid & 31;
    const int qr   = lane >> 2;
    const int qc   = lane & 3;

    const int r1 = row0 + wid * 16 + qr;
    const int bh = b * 16 + h;

    uint32_t aq[4][4];
    {
        const __half2 sc2 = __float2half2_rn(0.03125f);
        const uint32_t* q1 = qk + (long long)(b * T_ + r1) * 1024 + h * 64;
        const uint32_t* q2 = q1 + 8 * 1024;
#pragma unroll
        for (int kt = 0; kt < 4; kt++) {
            aq[kt][0] = hscale(q1[kt * 8 + qc], sc2);
            aq[kt][1] = hscale(q2[kt * 8 + qc], sc2);
            aq[kt][2] = hscale(q1[kt * 8 + qc + 4], sc2);
            aq[kt][3] = hscale(q2[kt * 8 + qc + 4], sc2);
        }
    }

    float o[8][4];
#pragma unroll
    for (int nt = 0; nt < 8; nt++)
#pragma unroll
        for (int t = 0; t < 4; t++) o[nt][t] = 0.f;
    float m0 = -1e30f, m1 = -1e30f, l0 = 0.f, l1 = 0.f;

    const int ntiles = (row0 >> 6) + 2;

    auto issue = [&](int j, int buf) {
        uint32_t* ks = Kb + buf * KVSZ;
        uint32_t* vs = Vb + buf * KVSZ;
#pragma unroll
        for (int i = 0; i < 2; i++) {
            int e = tid + i * 256;
            int kr = e >> 3, qd = e & 7;
            cpa16(&ks[kr * KVW + qd * 4],
                  qk + (long long)(b * T_ + j * 64 + kr) * 1024 + h * 64 + 32 + qd * 4);
        }
#pragma unroll
        for (int i = 0; i < 2; i++) {
            int e = tid + i * 256;
            int dd = e >> 3, qd = e & 7;
            cpa16(&vs[dd * KVW + qd * 4],
                  vtw + (long long)(bh * 64 + dd) * 512 + j * 32 + qd * 4);
        }
        cpa_commit();
    };

    issue(0, 0);
    for (int j = 0; j < ntiles; j++) {
        if (j + 1 < ntiles) { issue(j + 1, (j + 1) & 1); cpa_wait<1>(); }
        else                { cpa_wait<0>(); }
        __syncthreads();

        const uint32_t* ks = Kb + (j & 1) * KVSZ;
        const uint32_t* vs = Vb + (j & 1) * KVSZ;

        float s[8][4];
#pragma unroll
        for (int nt = 0; nt < 8; nt++)
#pragma unroll
            for (int t = 0; t < 4; t++) s[nt][t] = 0.f;
#pragma unroll
        for (int kt = 0; kt < 4; kt++) {
            uint32_t bfr[8][2];
#pragma unroll
            for (int nt = 0; nt < 8; nt++) {
                bfr[nt][0] = ks[(nt * 8 + qr) * KVW + kt * 8 + qc];
                bfr[nt][1] = ks[(nt * 8 + qr) * KVW + kt * 8 + qc + 4];
            }
#pragma unroll
            for (int nt = 0; nt < 8; nt++)
                MMA_F16(s[nt][0], s[nt][1], s[nt][2], s[nt][3],
                        aq[kt][0], aq[kt][1], aq[kt][2], aq[kt][3],
                        bfr[nt][0], bfr[nt][1]);
        }

        const int r2 = r1 + 8;
        if (j * 64 + 63 > row0 + wid * 16) {
#pragma unroll
            for (int nt = 0; nt < 8; nt++) {
                int c = j * 64 + nt * 8 + qc * 2;
                if (c     > r1) s[nt][0] = -1e30f;
                if (c + 1 > r1) s[nt][1] = -1e30f;
                if (c     > r2) s[nt][2] = -1e30f;
                if (c + 1 > r2) s[nt][3] = -1e30f;
            }
        }

        float nm0 = m0, nm1 = m1;
#pragma unroll
        for (int nt = 0; nt < 8; nt++) {
            nm0 = fmaxf(nm0, fmaxf(s[nt][0], s[nt][1]));
            nm1 = fmaxf(nm1, fmaxf(s[nt][2], s[nt][3]));
        }
        nm0 = fmaxf(nm0, __shfl_xor_sync(0xffffffff, nm0, 1));
        nm0 = fmaxf(nm0, __shfl_xor_sync(0xffffffff, nm0, 2));
        nm1 = fmaxf(nm1, __shfl_xor_sync(0xffffffff, nm1, 1));
        nm1 = fmaxf(nm1, __shfl_xor_sync(0xffffffff, nm1, 2));

        float f0 = __expf(m0 - nm0), f1 = __expf(m1 - nm1);
        m0 = nm0; m1 = nm1;

        uint32_t* pw = Ps + wid * 512;
        float rs0 = 0.f, rs1 = 0.f;
        __syncwarp();
#pragma unroll
        for (int nt = 0; nt < 8; nt++) {
            float p0 = __expf(s[nt][0] - nm0);
            float p1 = __expf(s[nt][1] - nm0);
            float p2 = __expf(s[nt][2] - nm1);
            float p3 = __expf(s[nt][3] - nm1);
            rs0 += p0 + p1; rs1 += p2 + p3;
            int base = ((nt >> 1) * 32 + lane) * 4 + 2 * (nt & 1);
            pw[base]     = h2(p0, p1);
            pw[base + 1] = h2(p2, p3);
        }
        rs0 += __shfl_xor_sync(0xffffffff, rs0, 1);
        rs0 += __shfl_xor_sync(0xffffffff, rs0, 2);
        rs1 += __shfl_xor_sync(0xffffffff, rs1, 1);
        rs1 += __shfl_xor_sync(0xffffffff, rs1, 2);
        l0 = l0 * f0 + rs0;
        l1 = l1 * f1 + rs1;

#pragma unroll
        for (int nt = 0; nt < 8; nt++) {
            o[nt][0] *= f0; o[nt][1] *= f0;
            o[nt][2] *= f1; o[nt][3] *= f1;
        }
        __syncwarp();

#pragma unroll
        for (int kt = 0; kt < 4; kt++) {
            uint4 a = *(const uint4*)&pw[(kt * 32 + lane) * 4];
            uint32_t bfr[8][2];
#pragma unroll
            for (int ni = 0; ni < 8; ni++) {
                bfr[ni][0] = vs[(ni * 8 + qr) * KVW + kt * 8 + qc];
                bfr[ni][1] = vs[(ni * 8 + qr) * KVW + kt * 8 + qc + 4];
            }
#pragma unroll
            for (int ni = 0; ni < 8; ni++)
                MMA_F16(o[ni][0], o[ni][1], o[ni][2], o[ni][3],
                        a.x, a.y, a.z, a.w, bfr[ni][0], bfr[ni][1]);
        }
        __syncthreads();
    }

    float i0 = 1.f / l0, i1 = 1.f / l1;
    long long tb = ((long long)((b * 8 + blockIdx.x) * 16 + h)) * 4096;
    int base = wid * 512 + (qr * 4 + qc) * 4;
#pragma unroll
    for (int nt = 0; nt < 8; nt++) {
        long long off = tb + base + (nt >> 1) * 128 + 2 * (nt & 1);
        oc[off]     = h2(o[nt][0] * i0, o[nt][1] * i0);
        oc[off + 1] = h2(o[nt][2] * i1, o[nt][3] * i1);
    }
}

// ---------------------------------------------------------------------------
__global__ void embed_kernel(const int* __restrict__ idx,
                             const float* __restrict__ tok,
                             const float* __restrict__ pos,
                             float* __restrict__ x)
{
    int row = blockIdx.x;
    int t   = row & (T_ - 1);
    int tk  = idx[row];
    const float* te = tok + (long long)tk * E_;
    const float* pe = pos + (long long)t  * E_;
    float* xr = x + (long long)row * E_;
    for (int c = threadIdx.x; c < E_; c += blockDim.x)
        xr[c] = te[c] + pe[c];
}

__global__ void ln_kernel(const float* __restrict__ x, uint32_t* __restrict__ yp,
                          const float* __restrict__ sc, const float* __restrict__ bi)
{
    int row = blockIdx.x;
    int tid = threadIdx.x;
    float4 f = ((const float4*)(x + (long long)row * E_))[tid];
    float sum = f.x + f.y + f.z + f.w;
    float sq  = f.x * f.x + f.y * f.y + f.z * f.z + f.w * f.w;
    __shared__ float s1[256], s2[256];
    s1[tid] = sum; s2[tid] = sq;
    __syncthreads();
    for (int st = 128; st > 0; st >>= 1) {
        if (tid < st) { s1[tid] += s1[tid + st]; s2[tid] += s2[tid + st]; }
        __syncthreads();
    }
    float mean = s1[0] * (1.f / E_);
    float var  = s2[0] * (1.f / E_) - mean * mean;
    float inv  = rsqrtf(var + 1e-5f);

    int c = tid * 4;
    float y0 = (f.x - mean) * inv * sc[c]     + bi[c];
    float y1 = (f.y - mean) * inv * sc[c + 1] + bi[c + 1];
    float y2 = (f.z - mean) * inv * sc[c + 2] + bi[c + 2];
    float y3 = (f.w - mean) * inv * sc[c + 3] + bi[c + 3];

    int kk = c & 63;
    long long tb = ((long long)(row >> 7) * 16 + (c >> 6)) * 4096;
    int base = (((row & 127) >> 4) * 4 + (kk >> 4)) * 128
             + ((row & 7) * 4 + ((kk & 7) >> 1)) * 4
             + ((row >> 3) & 1) + 2 * ((kk >> 3) & 1);
    yp[tb + base]     = h2(y0, y1);
    yp[tb + base + 4] = h2(y2, y3);
}

// Merge 250 per-block partials per row -> weighted CE
__global__ void loss_rows_kernel(const float* __restrict__ logits,
                                 const float2* __restrict__ part,
                                 const int* __restrict__ tgt,
                                 float* __restrict__ rl)
{
    int row = blockIdx.x;
    int tid = threadIdx.x;
    float m = -1e30f, s = 0.f;
    if (tid < NVB) {
        float2 p = part[(long long)row * NVB + tid];
        m = p.x; s = p.y;
    }
    __shared__ float sm[256], ss[256];
    sm[tid] = m; ss[tid] = s;
    __syncthreads();
    for (int st = 128; st > 0; st >>= 1) {
        if (tid < st) {
            float m2 = sm[tid + st], s2 = ss[tid + st];
            float nm = fmaxf(sm[tid], m2);
            ss[tid] = ss[tid] * __expf(sm[tid] - nm) + s2 * __expf(m2 - nm);
            sm[tid] = nm;
        }
        __syncthreads();
    }
    if (tid == 0) {
        float lse = sm[0] + __logf(ss[0]);
        int t = tgt[row];
        float ce = lse - logits[(long long)row * V_ + t];
        float w = 1.f;
        if (t == 4 || t == 3 || t == 1) w = 1.5f;
        if (t == 2) w = 2.0f;
        if (t == 0) w = 0.1f;
        rl[row] = ce * w;
    }
}

__global__ void loss_reduce_kernel(const float* __restrict__ rl, float* __restrict__ out)
{
    __shared__ float sm[1024];
    float s = 0.f;
    for (int i = threadIdx.x; i < BT_; i += 1024) s += rl[i];
    sm[threadIdx.x] = s;
    __syncthreads();
    for (int st = 512; st > 0; st >>= 1) {
        if (threadIdx.x < st) sm[threadIdx.x] += sm[threadIdx.x + st];
        __syncthreads();
    }
    if (threadIdx.x == 0) *out = sm[0] * (1.f / BT_);
}

// ---------------------------------------------------------------------------
static inline void gemm0(const uint32_t* A, const uint32_t* Bp,
                         float* Cf, int ldc, int M, int N, int K,
                         const float* bias, const float* resid, int relu)
{
    dim3 grid(N / 128, M / 128, 1);
    mma_gemm<0><<<grid, 256, G_SMEM>>>(A, Bp, Cf, nullptr, nullptr, ldc, M, N, K,
                                       bias, resid, relu);
}

static inline void gemm1(const uint32_t* A, const uint32_t* Bp,
                         uint32_t* Cw, int M, int N, int K, const float* bias)
{
    dim3 grid(N / 128, M / 128, 1);
    mma_gemm<1><<<grid, 256, G_SMEM>>>(A, Bp, nullptr, Cw, nullptr, 0, M, N, K,
                                       bias, nullptr, 1);
}

static inline void gemm2(const uint32_t* A, const uint32_t* Bp,
                         uint32_t* qk, uint32_t* vt, int M, int N, int K)
{
    dim3 grid(N / 128, M / 128, 1);
    mma_gemm<2><<<grid, 256, G_SMEM>>>(A, Bp, (float*)vt, qk, nullptr, 0, M, N, K,
                                       nullptr, nullptr, 0);
}

static inline void gemm3(const uint32_t* A, const uint32_t* Bp,
                         float* Cf, float2* part, int M, int N, int K,
                         const float* bias)
{
    dim3 grid(N / 128, M / 128, 1);
    mma_gemm<3><<<grid, 256, G_SMEM>>>(A, Bp, Cf, nullptr, part, N, M, N, K,
                                       bias, nullptr, 0);
}

extern "C" void kernel_launch(void* const* d_in, const int* in_sizes, int n_in,
                              void* d_out, int out_size)
{
    const int*   idx = (const int*)d_in[0];
    const int*   tgt = (const int*)d_in[1];
    const float* tok = (const float*)d_in[2];
    const float* pos = (const float*)d_in[3];
    const float* Wq  = (const float*)d_in[4];
    const float* Wk  = (const float*)d_in[5];
    const float* Wv  = (const float*)d_in[6];
    const float* Wp  = (const float*)d_in[7];
    const float* bp  = (const float*)d_in[8];
    const float* W1  = (const float*)d_in[9];
    const float* b1  = (const float*)d_in[10];
    const float* W2  = (const float*)d_in[11];
    const float* b2  = (const float*)d_in[12];
    const float* l1s = (const float*)d_in[13];
    const float* l1b = (const float*)d_in[14];
    const float* l2s = (const float*)d_in[15];
    const float* l2b = (const float*)d_in[16];
    const float* lfs = (const float*)d_in[17];
    const float* lfb = (const float*)d_in[18];
    const float* Wh  = (const float*)d_in[19];
    const float* bh  = (const float*)d_in[20];
    float* out = (float*)d_out;

    cudaFuncSetAttribute(mma_gemm<0>, cudaFuncAttributeMaxDynamicSharedMemorySize, G_SMEM);
    cudaFuncSetAttribute(mma_gemm<1>, cudaFuncAttributeMaxDynamicSharedMemorySize, G_SMEM);
    cudaFuncSetAttribute(mma_gemm<2>, cudaFuncAttributeMaxDynamicSharedMemorySize, G_SMEM);
    cudaFuncSetAttribute(mma_gemm<3>, cudaFuncAttributeMaxDynamicSharedMemorySize, G_SMEM);
    cudaFuncSetAttribute(flash_kernel, cudaFuncAttributeMaxDynamicSharedMemorySize, FL_SMEM);

    float *x, *rl;
    float2* part;
    uint32_t *h, *qk, *vt, *oc, *ff;
    uint32_t *wqkv, *wp, *w1, *w2, *wh;
    cudaGetSymbolAddress((void**)&x,    g_x);
    cudaGetSymbolAddress((void**)&h,    g_h);
    cudaGetSymbolAddress((void**)&qk,   g_qk);
    cudaGetSymbolAddress((void**)&vt,   g_vt);
    cudaGetSymbolAddress((void**)&oc,   g_oc);
    cudaGetSymbolAddress((void**)&ff,   g_ff);
    cudaGetSymbolAddress((void**)&part, g_part);
    cudaGetSymbolAddress((void**)&rl,   g_rl);
    cudaGetSymbolAddress((void**)&wqkv, g_wqkv);
    cudaGetSymbolAddress((void**)&wp,   g_wp);
    cudaGetSymbolAddress((void**)&w1,   g_w1);
    cudaGetSymbolAddress((void**)&w2,   g_w2);
    cudaGetSymbolAddress((void**)&wh,   g_wh);

    // Weight prep (fp16 fragment tiles)
    pack_qkv_kernel<<<dim3(QKVW / 128, E_ / 64, L_), 256>>>(Wq, Wk, Wv, wqkv);
    pack_w_kernel<<<dim3(E_ / 128, E_ / 64, L_), 256>>>(Wp, wp, E_, E_);
    pack_w_kernel<<<dim3(FF_ / 128, E_ / 64, L_), 256>>>(W1, w1, FF_, E_);
    pack_w_kernel<<<dim3(E_ / 128, FF_ / 64, L_), 256>>>(W2, w2, E_, FF_);
    pack_w_kernel<<<dim3(V_ / 128, E_ / 64, 1), 256>>>(Wh, wh, V_, E_);

    embed_kernel<<<BT_, 256>>>(idx, tok, pos, x);

    for (int l = 0; l < L_; l++) {
        ln_kernel<<<BT_, 256>>>(x, h, l1s + l * E_, l1b + l * E_);

        gemm2(h, wqkv + (long long)l * E_ * QKVW / 2, qk, vt, BT_, QKVW, E_);

        flash_kernel<<<dim3(T_ / 128, B_ * H_), 256, FL_SMEM>>>(qk, vt, oc);

        gemm0(oc, wp + (long long)l * E_ * E_ / 2, x, E_,
              BT_, E_, E_, bp + l * E_, x, 0);

        ln_kernel<<<BT_, 256>>>(x, h, l2s + l * E_, l2b + l * E_);

        gemm1(h, w1 + (long long)l * E_ * FF_ / 2, ff,
              BT_, FF_, E_, b1 + l * FF_);

        gemm0(ff, w2 + (long long)l * FF_ * E_ / 2, x, E_,
              BT_, E_, FF_, b2 + l * E_, x, 0);
    }

    ln_kernel<<<BT_, 256>>>(x, h, lfs, lfb);

    // head GEMM with fused partial softmax stats
    gemm3(h, wh, out, part, BT_, V_, E_, bh);

    loss_rows_kernel<<<BT_, 256>>>(out, part, tgt, rl);
    if ((long long)out_size >= (long long)BT_ * V_ + 1)
        loss_reduce_kernel<<<1, 1024>>>(rl, out + (long long)BT_ * V_);
}

// round 16
// speedup vs baseline: 1.4821x; 1.4821x over previous
#include <cuda_runtime.h>
#include <cuda_fp16.h>
#include <math.h>
#include <stdint.h>

// Problem config
#define E_   1024
#define H_   16
#define D_   64
#define L_   6
#define FF_  4096
#define B_   4
#define T_   1024
#define BT_  4096
#define V_   32000
#define QKVW 3072
#define NPART 1000           // per-row loss partials: 250 colblocks x 4 warpcols

// Activation scratch
__device__ __align__(16) float    g_x[BT_ * E_];
__device__ __align__(16) uint32_t g_h[BT_ * E_ / 2];
__device__ __align__(16) uint32_t g_qk[BT_ * 1024];
__device__ __align__(16) uint32_t g_vt[B_ * H_ * 64 * T_ / 2];
__device__ __align__(16) uint32_t g_oc[BT_ * E_ / 2];
__device__ __align__(16) uint32_t g_ff[BT_ * FF_ / 2];
__device__ __align__(16) float2   g_part[(size_t)BT_ * NPART];
__device__ __align__(16) float    g_rl[BT_];

// Fragment-packed fp16 weights (tile = 64k x 128n = 4096 b32 words)
__device__ __align__(16) uint32_t g_wqkv[(size_t)L_ * E_ * QKVW / 2];
__device__ __align__(16) uint32_t g_wp[(size_t)L_ * E_ * E_ / 2];
__device__ __align__(16) uint32_t g_w1[(size_t)L_ * E_ * FF_ / 2];
__device__ __align__(16) uint32_t g_w2[(size_t)L_ * FF_ * E_ / 2];
__device__ __align__(16) uint32_t g_wh[(size_t)E_ * V_ / 2];

__device__ __forceinline__ uint32_t h2(float a, float b) {
    __half2 t = __floats2half2_rn(a, b);
    return *(uint32_t*)&t;
}
__device__ __forceinline__ uint32_t hscale(uint32_t u, __half2 s) {
    __half2 t = __hmul2(*(__half2*)&u, s);
    return *(uint32_t*)&t;
}

__device__ __forceinline__ void cpa16(void* s, const void* g) {
    uint32_t sa = (uint32_t)__cvta_generic_to_shared(s);
    asm volatile("cp.async.cg.shared.global [%0], [%1], 16;\n" :: "r"(sa), "l"(g));
}
__device__ __forceinline__ void cpa_commit() { asm volatile("cp.async.commit_group;\n"); }
template<int N> __device__ __forceinline__ void cpa_wait() {
    asm volatile("cp.async.wait_group %0;\n" :: "n"(N));
}

#define MMA_F16(d0,d1,d2,d3,a0,a1,a2,a3,b0,b1) \
    asm volatile("mma.sync.aligned.m16n8k16.row.col.f32.f16.f16.f32 " \
        "{%0,%1,%2,%3}, {%4,%5,%6,%7}, {%8,%9}, {%0,%1,%2,%3};\n" \
        : "+f"(d0), "+f"(d1), "+f"(d2), "+f"(d3) \
        : "r"(a0), "r"(a1), "r"(a2), "r"(a3), "r"(b0), "r"(b1))

// ---------------------------------------------------------------------------
// fp16 GEMM: 128x128 CTA tile, BK=64, 3-stage cp.async (R14 mainloop).
// OMODE 0: fp32 row-major out (+bias/resid/relu)
// OMODE 1: packed-A fp16 out (+bias, relu)
// OMODE 2: qkv split out (Q/K -> Cw rows, V -> (half*)Cf transposed)
// OMODE 3: head: fp32 logits out (+bias) AND per-warpcol partial (max, sumexp)
// ---------------------------------------------------------------------------
#define TSZ 4096
#define G_SMEM (3 * 2 * TSZ * 4)

template<int OMODE>
__global__ __launch_bounds__(256, 2)
void mma_gemm(const uint32_t* __restrict__ Ap,
              const uint32_t* __restrict__ Bp,
              float* __restrict__ Cf,
              uint32_t* __restrict__ Cw,
              float2* __restrict__ part,
              int ldc, int M, int N, int K,
              const float* __restrict__ bias,
              const float* __restrict__ resid,
              int relu)
{
    extern __shared__ __align__(16) uint32_t dsm[];
    uint32_t* Abuf = dsm;
    uint32_t* Bbuf = dsm + 3 * TSZ;

    const int row0 = blockIdx.y * 128;
    const int col0 = blockIdx.x * 128;
    const int tid  = threadIdx.x;
    const int warp = tid >> 5;
    const int lane = tid & 31;
    const int wm   = (warp >> 2) * 64;
    const int wm16 = (warp >> 2) * 4;
    const int wn8  = (warp & 3) * 4;
    const int qr   = lane >> 2;
    const int qc   = lane & 3;

    const int ntn = N >> 7;
    const int nkt = K >> 6;
    const int mt  = row0 >> 7;

    float acc[4][4][4];
#pragma unroll
    for (int i = 0; i < 4; i++)
#pragma unroll
        for (int j = 0; j < 4; j++)
#pragma unroll
            for (int t = 0; t < 4; t++) acc[i][j][t] = 0.f;

    auto issue = [&](int it) {
        int buf = it % 3;
        uint32_t* as = Abuf + buf * TSZ;
        const uint32_t* at = Ap + ((long long)mt * nkt + it) * TSZ;
#pragma unroll
        for (int i = 0; i < 4; i++) {
            int e = tid + i * 256;
            cpa16(&as[e * 4], at + e * 4);
        }
        uint32_t* bs = Bbuf + buf * TSZ;
        const uint32_t* bt = Bp + ((long long)it * ntn + (col0 >> 7)) * TSZ;
#pragma unroll
        for (int i = 0; i < 4; i++) {
            int e = tid + i * 256;
            cpa16(&bs[e * 4], bt + e * 4);
        }
        cpa_commit();
    };

    issue(0);
    issue(1);

    for (int it = 0; it < nkt; it++) {
        if (it + 2 < nkt) issue(it + 2);
        else              cpa_commit();
        cpa_wait<2>();
        __syncthreads();

        const uint32_t* as = Abuf + (it % 3) * TSZ;
        const uint32_t* bs = Bbuf + (it % 3) * TSZ;

#pragma unroll
        for (int kt = 0; kt < 4; kt++) {
            uint4 a[4];
#pragma unroll
            for (int mi = 0; mi < 4; mi++)
                a[mi] = *(const uint4*)&as[((wm16 + mi) * 4 + kt) * 128 + lane * 4];
            uint32_t b[4][2];
#pragma unroll
            for (int ni = 0; ni < 4; ni++) {
                uint2 t2 = *(const uint2*)&bs[((wn8 + ni) * 4 + kt) * 64 + lane * 2];
                b[ni][0] = t2.x; b[ni][1] = t2.y;
            }
#pragma unroll
            for (int mi = 0; mi < 4; mi++)
#pragma unroll
                for (int ni = 0; ni < 4; ni++)
                    MMA_F16(acc[mi][ni][0], acc[mi][ni][1], acc[mi][ni][2], acc[mi][ni][3],
                            a[mi].x, a[mi].y, a[mi].z, a[mi].w,
                            b[ni][0], b[ni][1]);
        }
        __syncthreads();
    }

    if (OMODE == 0) {
#pragma unroll
        for (int mi = 0; mi < 4; mi++) {
#pragma unroll
            for (int ni = 0; ni < 4; ni++) {
#pragma unroll
                for (int half = 0; half < 2; half++) {
                    int r = row0 + wm + mi * 16 + qr + half * 8;
                    int c = col0 + (warp & 3) * 32 + ni * 8 + qc * 2;
                    float v0 = acc[mi][ni][half * 2];
                    float v1 = acc[mi][ni][half * 2 + 1];
                    if (bias) { v0 += bias[c]; v1 += bias[c + 1]; }
                    if (resid) {
                        float2 rr = *(const float2*)(resid + (long long)r * ldc + c);
                        v0 += rr.x; v1 += rr.y;
                    }
                    if (relu) { v0 = fmaxf(v0, 0.f); v1 = fmaxf(v1, 0.f); }
                    *(float2*)(Cf + (long long)r * ldc + c) = make_float2(v0, v1);
                }
            }
        }
    } else if (OMODE == 1) {
        float* stg = (float*)dsm;   // 128 x 130
#pragma unroll
        for (int mi = 0; mi < 4; mi++)
#pragma unroll
            for (int ni = 0; ni < 4; ni++)
#pragma unroll
                for (int half = 0; half < 2; half++) {
                    int r = wm + mi * 16 + qr + half * 8;
                    int c = (warp & 3) * 32 + ni * 8 + qc * 2;
                    *(float2*)&stg[r * 130 + c] =
                        make_float2(acc[mi][ni][half * 2], acc[mi][ni][half * 2 + 1]);
                }
        __syncthreads();
        const int nktC = N >> 6;
#pragma unroll
        for (int i = 0; i < 32; i++) {
            int g  = tid + i * 256;
            int tl = g >> 12;
            int W  = g & 4095;
            int chunk = W >> 9;
            int kt = (W >> 7) & 3;
            int ln = (W >> 2) & 31;
            int w  = W & 3;
            int m  = chunk * 16 + (ln >> 2) + (w & 1) * 8;
            int k  = kt * 16 + (w >> 1) * 8 + (ln & 3) * 2;
            int c  = tl * 64 + k;
            float v0 = stg[m * 130 + c]     + bias[col0 + c];
            float v1 = stg[m * 130 + c + 1] + bias[col0 + c + 1];
            v0 = fmaxf(v0, 0.f); v1 = fmaxf(v1, 0.f);
            Cw[((long long)mt * nktC + (col0 >> 6) + tl) * 4096 + W] = h2(v0, v1);
        }
    } else if (OMODE == 2) {
        __half* vh = (__half*)Cf;
#pragma unroll
        for (int mi = 0; mi < 4; mi++) {
#pragma unroll
            for (int ni = 0; ni < 4; ni++) {
#pragma unroll
                for (int half = 0; half < 2; half++) {
                    int r = row0 + wm + mi * 16 + qr + half * 8;
                    int c = col0 + (warp & 3) * 32 + ni * 8 + qc * 2;
                    float v0 = acc[mi][ni][half * 2];
                    float v1 = acc[mi][ni][half * 2 + 1];
                    int hh = c / 192;
                    int rem = c - hh * 192;
                    int sel = rem >> 6;
                    int d = rem & 63;
                    if (sel < 2) {
                        Cw[(long long)r * 1024 + hh * 64 + sel * 32 + (d >> 1)] = h2(v0, v1);
                    } else {
                        int bb = r >> 10, t = r & 1023;
                        long long base = (long long)((bb * 16 + hh) * 64 + d) * 1024 + t;
                        vh[base]        = __float2half_rn(v0);
                        vh[base + 1024] = __float2half_rn(v1);
                    }
                }
            }
        }
    } else {
        // OMODE 3: logits (+bias) + per-warpcol partial (max, sumexp), no smem
#pragma unroll
        for (int mi = 0; mi < 4; mi++) {
#pragma unroll
            for (int ni = 0; ni < 4; ni++) {
#pragma unroll
                for (int t = 0; t < 4; t++) {
                    int c = col0 + (warp & 3) * 32 + ni * 8 + qc * 2 + (t & 1);
                    acc[mi][ni][t] += bias[c];
                }
#pragma unroll
                for (int half = 0; half < 2; half++) {
                    int r = row0 + wm + mi * 16 + qr + half * 8;
                    int c = col0 + (warp & 3) * 32 + ni * 8 + qc * 2;
                    *(float2*)(Cf + (long long)r * ldc + c) =
                        make_float2(acc[mi][ni][half * 2], acc[mi][ni][half * 2 + 1]);
                }
            }
        }
        const int pcol = (col0 >> 7) * 4 + (warp & 3);
#pragma unroll
        for (int mi = 0; mi < 4; mi++) {
#pragma unroll
            for (int half = 0; half < 2; half++) {
                float m_t = -1e30f;
#pragma unroll
                for (int ni = 0; ni < 4; ni++)
                    m_t = fmaxf(m_t, fmaxf(acc[mi][ni][half * 2], acc[mi][ni][half * 2 + 1]));
                m_t = fmaxf(m_t, __shfl_xor_sync(0xffffffff, m_t, 1));
                m_t = fmaxf(m_t, __shfl_xor_sync(0xffffffff, m_t, 2));
                float s_t = 0.f;
#pragma unroll
                for (int ni = 0; ni < 4; ni++)
                    s_t += __expf(acc[mi][ni][half * 2] - m_t)
                         + __expf(acc[mi][ni][half * 2 + 1] - m_t);
                s_t += __shfl_xor_sync(0xffffffff, s_t, 1);
                s_t += __shfl_xor_sync(0xffffffff, s_t, 2);
                if (qc == 0) {
                    int r = row0 + wm + mi * 16 + qr + half * 8;
                    part[(long long)r * NPART + pcol] = make_float2(m_t, s_t);
                }
            }
        }
    }
}

// ---------------------------------------------------------------------------
// Weight packing: [K,N] fp32 -> fp16 fragment tiles (64k x 128n).
// ---------------------------------------------------------------------------
__global__ __launch_bounds__(256)
void pack_w_kernel(const float* __restrict__ src, uint32_t* __restrict__ dst,
                   int N, int K)
{
    const int nt = blockIdx.x, kc = blockIdx.y, l = blockIdx.z;
    src += (long long)l * K * N;
    dst += (long long)l * K * N / 2;
    __shared__ float sm[64][129];
    const int tid = threadIdx.x;
#pragma unroll
    for (int i = 0; i < 8; i++) {
        int e = tid + i * 256;
        int r = e >> 5, c4 = e & 31;
        float4 f = *(const float4*)(src + (long long)(kc * 64 + r) * N + nt * 128 + c4 * 4);
        sm[r][c4 * 4 + 0] = f.x; sm[r][c4 * 4 + 1] = f.y;
        sm[r][c4 * 4 + 2] = f.z; sm[r][c4 * 4 + 3] = f.w;
    }
    __syncthreads();
    uint32_t* o = dst + ((long long)kc * (N >> 7) + nt) * 4096;
#pragma unroll
    for (int i = 0; i < 16; i++) {
        int W = tid + i * 256;
        int ns = W >> 8;
        int kt = (W >> 6) & 3;
        int rem = W & 63;
        int ln = rem >> 1, w = rem & 1;
        int n = ns * 8 + (ln >> 2);
        int k = kt * 16 + w * 8 + (ln & 3) * 2;
        o[W] = h2(sm[k][n], sm[k + 1][n]);
    }
}

__global__ __launch_bounds__(256)
void pack_qkv_kernel(const float* __restrict__ Wq,
                     const float* __restrict__ Wk,
                     const float* __restrict__ Wv,
                     uint32_t* __restrict__ dst)
{
    const int nt = blockIdx.x, kc = blockIdx.y, l = blockIdx.z;
    __shared__ float sm[64][129];
    const int tid = threadIdx.x;
#pragma unroll
    for (int i = 0; i < 8; i++) {
        int e = tid + i * 256;
        int r = e >> 5, c4 = e & 31;
        int n = nt * 128 + c4 * 4;
        int h = n / 192;
        int rem = n - h * 192;
        int sel = rem >> 6;
        int d = rem & 63;
        const float* W = (sel == 0) ? Wq : (sel == 1) ? Wk : Wv;
        float4 f = *(const float4*)(W + (((long long)l * H_ + h) * E_ + kc * 64 + r) * D_ + d);
        sm[r][c4 * 4 + 0] = f.x; sm[r][c4 * 4 + 1] = f.y;
        sm[r][c4 * 4 + 2] = f.z; sm[r][c4 * 4 + 3] = f.w;
    }
    __syncthreads();
    uint32_t* o = dst + (long long)l * E_ * QKVW / 2
                + ((long long)kc * (QKVW >> 7) + nt) * 4096;
#pragma unroll
    for (int i = 0; i < 16; i++) {
        int W = tid + i * 256;
        int ns = W >> 8;
        int kt = (W >> 6) & 3;
        int rem = W & 63;
        int ln = rem >> 1, w = rem & 1;
        int n = ns * 8 + (ln >> 2);
        int k = kt * 16 + w * 8 + (ln & 3) * 2;
        o[W] = h2(sm[k][n], sm[k + 1][n]);
    }
}

// ---------------------------------------------------------------------------
// Fused causal flash attention, fp16 mma (unchanged from R14).
// ---------------------------------------------------------------------------
#define KVW 36
#define KVSZ (64 * KVW)
#define FL_SMEM ((4 * KVSZ + 4096) * 4)

__global__ __launch_bounds__(256, 2)
void flash_kernel(const uint32_t* __restrict__ qk,
                  const uint32_t* __restrict__ vtw,
                  uint32_t* __restrict__ oc)
{
    extern __shared__ __align__(16) uint32_t fsm[];
    uint32_t* Kb = fsm;
    uint32_t* Vb = fsm + 2 * KVSZ;
    uint32_t* Ps = fsm + 4 * KVSZ;

    const int row0 = blockIdx.x * 128;
    const int b    = blockIdx.y >> 4;
    const int h    = blockIdx.y & 15;
    const int tid  = threadIdx.x;
    const int wid  = tid >> 5;
    const int lane = tid & 31;
    const int qr   = lane >> 2;
    const int qc   = lane & 3;

    const int r1 = row0 + wid * 16 + qr;
    const int bh = b * 16 + h;

    uint32_t aq[4][4];
    {
        const __half2 sc2 = __float2half2_rn(0.03125f);
        const uint32_t* q1 = qk + (long long)(b * T_ + r1) * 1024 + h * 64;
        const uint32_t* q2 = q1 + 8 * 1024;
#pragma unroll
        for (int kt = 0; kt < 4; kt++) {
            aq[kt][0] = hscale(q1[kt * 8 + qc], sc2);
            aq[kt][1] = hscale(q2[kt * 8 + qc], sc2);
            aq[kt][2] = hscale(q1[kt * 8 + qc + 4], sc2);
            aq[kt][3] = hscale(q2[kt * 8 + qc + 4], sc2);
        }
    }

    float o[8][4];
#pragma unroll
    for (int nt = 0; nt < 8; nt++)
#pragma unroll
        for (int t = 0; t < 4; t++) o[nt][t] = 0.f;
    float m0 = -1e30f, m1 = -1e30f, l0 = 0.f, l1 = 0.f;

    const int ntiles = (row0 >> 6) + 2;

    auto issue = [&](int j, int buf) {
        uint32_t* ks = Kb + buf * KVSZ;
        uint32_t* vs = Vb + buf * KVSZ;
#pragma unroll
        for (int i = 0; i < 2; i++) {
            int e = tid + i * 256;
            int kr = e >> 3, qd = e & 7;
            cpa16(&ks[kr * KVW + qd * 4],
                  qk + (long long)(b * T_ + j * 64 + kr) * 1024 + h * 64 + 32 + qd * 4);
        }
#pragma unroll
        for (int i = 0; i < 2; i++) {
            int e = tid + i * 256;
            int dd = e >> 3, qd = e & 7;
            cpa16(&vs[dd * KVW + qd * 4],
                  vtw + (long long)(bh * 64 + dd) * 512 + j * 32 + qd * 4);
        }
        cpa_commit();
    };

    issue(0, 0);
    for (int j = 0; j < ntiles; j++) {
        if (j + 1 < ntiles) { issue(j + 1, (j + 1) & 1); cpa_wait<1>(); }
        else                { cpa_wait<0>(); }
        __syncthreads();

        const uint32_t* ks = Kb + (j & 1) * KVSZ;
        const uint32_t* vs = Vb + (j & 1) * KVSZ;

        float s[8][4];
#pragma unroll
        for (int nt = 0; nt < 8; nt++)
#pragma unroll
            for (int t = 0; t < 4; t++) s[nt][t] = 0.f;
#pragma unroll
        for (int kt = 0; kt < 4; kt++) {
            uint32_t bfr[8][2];
#pragma unroll
            for (int nt = 0; nt < 8; nt++) {
                bfr[nt][0] = ks[(nt * 8 + qr) * KVW + kt * 8 + qc];
                bfr[nt][1] = ks[(nt * 8 + qr) * KVW + kt * 8 + qc + 4];
            }
#pragma unroll
            for (int nt = 0; nt < 8; nt++)
                MMA_F16(s[nt][0], s[nt][1], s[nt][2], s[nt][3],
                        aq[kt][0], aq[kt][1], aq[kt][2], aq[kt][3],
                        bfr[nt][0], bfr[nt][1]);
        }

        const int r2 = r1 + 8;
        if (j * 64 + 63 > row0 + wid * 16) {
#pragma unroll
            for (int nt = 0; nt < 8; nt++) {
                int c = j * 64 + nt * 8 + qc * 2;
                if (c     > r1) s[nt][0] = -1e30f;
                if (c + 1 > r1) s[nt][1] = -1e30f;
                if (c     > r2) s[nt][2] = -1e30f;
                if (c + 1 > r2) s[nt][3] = -1e30f;
            }
        }

        float nm0 = m0, nm1 = m1;
#pragma unroll
        for (int nt = 0; nt < 8; nt++) {
            nm0 = fmaxf(nm0, fmaxf(s[nt][0], s[nt][1]));
            nm1 = fmaxf(nm1, fmaxf(s[nt][2], s[nt][3]));
        }
        nm0 = fmaxf(nm0, __shfl_xor_sync(0xffffffff, nm0, 1));
        nm0 = fmaxf(nm0, __shfl_xor_sync(0xffffffff, nm0, 2));
        nm1 = fmaxf(nm1, __shfl_xor_sync(0xffffffff, nm1, 1));
        nm1 = fmaxf(nm1, __shfl_xor_sync(0xffffffff, nm1, 2));

        float f0 = __expf(m0 - nm0), f1 = __expf(m1 - nm1);
        m0 = nm0; m1 = nm1;

        uint32_t* pw = Ps + wid * 512;
        float rs0 = 0.f, rs1 = 0.f;
        __syncwarp();
#pragma unroll
        for (int nt = 0; nt < 8; nt++) {
            float p0 = __expf(s[nt][0] - nm0);
            float p1 = __expf(s[nt][1] - nm0);
            float p2 = __expf(s[nt][2] - nm1);
            float p3 = __expf(s[nt][3] - nm1);
            rs0 += p0 + p1; rs1 += p2 + p3;
            int base = ((nt >> 1) * 32 + lane) * 4 + 2 * (nt & 1);
            pw[base]     = h2(p0, p1);
            pw[base + 1] = h2(p2, p3);
        }
        rs0 += __shfl_xor_sync(0xffffffff, rs0, 1);
        rs0 += __shfl_xor_sync(0xffffffff, rs0, 2);
        rs1 += __shfl_xor_sync(0xffffffff, rs1, 1);
        rs1 += __shfl_xor_sync(0xffffffff, rs1, 2);
        l0 = l0 * f0 + rs0;
        l1 = l1 * f1 + rs1;

#pragma unroll
        for (int nt = 0; nt < 8; nt++) {
            o[nt][0] *= f0; o[nt][1] *= f0;
            o[nt][2] *= f1; o[nt][3] *= f1;
        }
        __syncwarp();

#pragma unroll
        for (int kt = 0; kt < 4; kt++) {
            uint4 a = *(const uint4*)&pw[(kt * 32 + lane) * 4];
            uint32_t bfr[8][2];
#pragma unroll
            for (int ni = 0; ni < 8; ni++) {
                bfr[ni][0] = vs[(ni * 8 + qr) * KVW + kt * 8 + qc];
                bfr[ni][1] = vs[(ni * 8 + qr) * KVW + kt * 8 + qc + 4];
            }
#pragma unroll
            for (int ni = 0; ni < 8; ni++)
                MMA_F16(o[ni][0], o[ni][1], o[ni][2], o[ni][3],
                        a.x, a.y, a.z, a.w, bfr[ni][0], bfr[ni][1]);
        }
        __syncthreads();
    }

    float i0 = 1.f / l0, i1 = 1.f / l1;
    long long tb = ((long long)((b * 8 + blockIdx.x) * 16 + h)) * 4096;
    int base = wid * 512 + (qr * 4 + qc) * 4;
#pragma unroll
    for (int nt = 0; nt < 8; nt++) {
        long long off = tb + base + (nt >> 1) * 128 + 2 * (nt & 1);
        oc[off]     = h2(o[nt][0] * i0, o[nt][1] * i0);
        oc[off + 1] = h2(o[nt][2] * i1, o[nt][3] * i1);
    }
}

// ---------------------------------------------------------------------------
__global__ void embed_kernel(const int* __restrict__ idx,
                             const float* __restrict__ tok,
                             const float* __restrict__ pos,
                             float* __restrict__ x)
{
    int row = blockIdx.x;
    int t   = row & (T_ - 1);
    int tk  = idx[row];
    const float* te = tok + (long long)tk * E_;
    const float* pe = pos + (long long)t  * E_;
    float* xr = x + (long long)row * E_;
    for (int c = threadIdx.x; c < E_; c += blockDim.x)
        xr[c] = te[c] + pe[c];
}

__global__ void ln_kernel(const float* __restrict__ x, uint32_t* __restrict__ yp,
                          const float* __restrict__ sc, const float* __restrict__ bi)
{
    int row = blockIdx.x;
    int tid = threadIdx.x;
    float4 f = ((const float4*)(x + (long long)row * E_))[tid];
    float sum = f.x + f.y + f.z + f.w;
    float sq  = f.x * f.x + f.y * f.y + f.z * f.z + f.w * f.w;
    __shared__ float s1[256], s2[256];
    s1[tid] = sum; s2[tid] = sq;
    __syncthreads();
    for (int st = 128; st > 0; st >>= 1) {
        if (tid < st) { s1[tid] += s1[tid + st]; s2[tid] += s2[tid + st]; }
        __syncthreads();
    }
    float mean = s1[0] * (1.f / E_);
    float var  = s2[0] * (1.f / E_) - mean * mean;
    float inv  = rsqrtf(var + 1e-5f);

    int c = tid * 4;
    float y0 = (f.x - mean) * inv * sc[c]     + bi[c];
    float y1 = (f.y - mean) * inv * sc[c + 1] + bi[c + 1];
    float y2 = (f.z - mean) * inv * sc[c + 2] + bi[c + 2];
    float y3 = (f.w - mean) * inv * sc[c + 3] + bi[c + 3];

    int kk = c & 63;
    long long tb = ((long long)(row >> 7) * 16 + (c >> 6)) * 4096;
    int base = (((row & 127) >> 4) * 4 + (kk >> 4)) * 128
             + ((row & 7) * 4 + ((kk & 7) >> 1)) * 4
             + ((row >> 3) & 1) + 2 * ((kk >> 3) & 1);
    yp[tb + base]     = h2(y0, y1);
    yp[tb + base + 4] = h2(y2, y3);
}

// Merge NPART per-(block,warpcol) partials per row -> weighted CE
__global__ void loss_rows_kernel(const float* __restrict__ logits,
                                 const float2* __restrict__ part,
                                 const int* __restrict__ tgt,
                                 float* __restrict__ rl)
{
    int row = blockIdx.x;
    int tid = threadIdx.x;
    float m = -1e30f, s = 0.f;
    const float2* pr = part + (long long)row * NPART;
    for (int i = tid; i < NPART; i += 256) {
        float2 p = pr[i];
        float nm = fmaxf(m, p.x);
        s = s * __expf(m - nm) + p.y * __expf(p.x - nm);
        m = nm;
    }
    __shared__ float sm[256], ss[256];
    sm[tid] = m; ss[tid] = s;
    __syncthreads();
    for (int st = 128; st > 0; st >>= 1) {
        if (tid < st) {
            float m2 = sm[tid + st], s2 = ss[tid + st];
            float nm = fmaxf(sm[tid], m2);
            ss[tid] = ss[tid] * __expf(sm[tid] - nm) + s2 * __expf(m2 - nm);
            sm[tid] = nm;
        }
        __syncthreads();
    }
    if (tid == 0) {
        float lse = sm[0] + __logf(ss[0]);
        int t = tgt[row];
        float ce = lse - logits[(long long)row * V_ + t];
        float w = 1.f;
        if (t == 4 || t == 3 || t == 1) w = 1.5f;
        if (t == 2) w = 2.0f;
        if (t == 0) w = 0.1f;
        rl[row] = ce * w;
    }
}

__global__ void loss_reduce_kernel(const float* __restrict__ rl, float* __restrict__ out)
{
    __shared__ float sm[1024];
    float s = 0.f;
    for (int i = threadIdx.x; i < BT_; i += 1024) s += rl[i];
    sm[threadIdx.x] = s;
    __syncthreads();
    for (int st = 512; st > 0; st >>= 1) {
        if (threadIdx.x < st) sm[threadIdx.x] += sm[threadIdx.x + st];
        __syncthreads();
    }
    if (threadIdx.x == 0) *out = sm[0] * (1.f / BT_);
}

// ---------------------------------------------------------------------------
static inline void gemm0(const uint32_t* A, const uint32_t* Bp,
                         float* Cf, int ldc, int M, int N, int K,
                         const float* bias, const float* resid, int relu)
{
    dim3 grid(N / 128, M / 128, 1);
    mma_gemm<0><<<grid, 256, G_SMEM>>>(A, Bp, Cf, nullptr, nullptr, ldc, M, N, K,
                                       bias, resid, relu);
}

static inline void gemm1(const uint32_t* A, const uint32_t* Bp,
                         uint32_t* Cw, int M, int N, int K, const float* bias)
{
    dim3 grid(N / 128, M / 128, 1);
    mma_gemm<1><<<grid, 256, G_SMEM>>>(A, Bp, nullptr, Cw, nullptr, 0, M, N, K,
                                       bias, nullptr, 1);
}

static inline void gemm2(const uint32_t* A, const uint32_t* Bp,
                         uint32_t* qk, uint32_t* vt, int M, int N, int K)
{
    dim3 grid(N / 128, M / 128, 1);
    mma_gemm<2><<<grid, 256, G_SMEM>>>(A, Bp, (float*)vt, qk, nullptr, 0, M, N, K,
                                       nullptr, nullptr, 0);
}

static inline void gemm3(const uint32_t* A, const uint32_t* Bp,
                         float* Cf, float2* part, int M, int N, int K,
                         const float* bias)
{
    dim3 grid(N / 128, M / 128, 1);
    mma_gemm<3><<<grid, 256, G_SMEM>>>(A, Bp, Cf, nullptr, part, N, M, N, K,
                                       bias, nullptr, 0);
}

extern "C" void kernel_launch(void* const* d_in, const int* in_sizes, int n_in,
                              void* d_out, int out_size)
{
    const int*   idx = (const int*)d_in[0];
    const int*   tgt = (const int*)d_in[1];
    const float* tok = (const float*)d_in[2];
    const float* pos = (const float*)d_in[3];
    const float* Wq  = (const float*)d_in[4];
    const float* Wk  = (const float*)d_in[5];
    const float* Wv  = (const float*)d_in[6];
    const float* Wp  = (const float*)d_in[7];
    const float* bp  = (const float*)d_in[8];
    const float* W1  = (const float*)d_in[9];
    const float* b1  = (const float*)d_in[10];
    const float* W2  = (const float*)d_in[11];
    const float* b2  = (const float*)d_in[12];
    const float* l1s = (const float*)d_in[13];
    const float* l1b = (const float*)d_in[14];
    const float* l2s = (const float*)d_in[15];
    const float* l2b = (const float*)d_in[16];
    const float* lfs = (const float*)d_in[17];
    const float* lfb = (const float*)d_in[18];
    const float* Wh  = (const float*)d_in[19];
    const float* bh  = (const float*)d_in[20];
    float* out = (float*)d_out;

    cudaFuncSetAttribute(mma_gemm<0>, cudaFuncAttributeMaxDynamicSharedMemorySize, G_SMEM);
    cudaFuncSetAttribute(mma_gemm<1>, cudaFuncAttributeMaxDynamicSharedMemorySize, G_SMEM);
    cudaFuncSetAttribute(mma_gemm<2>, cudaFuncAttributeMaxDynamicSharedMemorySize, G_SMEM);
    cudaFuncSetAttribute(mma_gemm<3>, cudaFuncAttributeMaxDynamicSharedMemorySize, G_SMEM);
    cudaFuncSetAttribute(flash_kernel, cudaFuncAttributeMaxDynamicSharedMemorySize, FL_SMEM);

    float *x, *rl;
    float2* part;
    uint32_t *h, *qk, *vt, *oc, *ff;
    uint32_t *wqkv, *wp, *w1, *w2, *wh;
    cudaGetSymbolAddress((void**)&x,    g_x);
    cudaGetSymbolAddress((void**)&h,    g_h);
    cudaGetSymbolAddress((void**)&qk,   g_qk);
    cudaGetSymbolAddress((void**)&vt,   g_vt);
    cudaGetSymbolAddress((void**)&oc,   g_oc);
    cudaGetSymbolAddress((void**)&ff,   g_ff);
    cudaGetSymbolAddress((void**)&part, g_part);
    cudaGetSymbolAddress((void**)&rl,   g_rl);
    cudaGetSymbolAddress((void**)&wqkv, g_wqkv);
    cudaGetSymbolAddress((void**)&wp,   g_wp);
    cudaGetSymbolAddress((void**)&w1,   g_w1);
    cudaGetSymbolAddress((void**)&w2,   g_w2);
    cudaGetSymbolAddress((void**)&wh,   g_wh);

    // Weight prep (fp16 fragment tiles)
    pack_qkv_kernel<<<dim3(QKVW / 128, E_ / 64, L_), 256>>>(Wq, Wk, Wv, wqkv);
    pack_w_kernel<<<dim3(E_ / 128, E_ / 64, L_), 256>>>(Wp, wp, E_, E_);
    pack_w_kernel<<<dim3(FF_ / 128, E_ / 64, L_), 256>>>(W1, w1, FF_, E_);
    pack_w_kernel<<<dim3(E_ / 128, FF_ / 64, L_), 256>>>(W2, w2, E_, FF_);
    pack_w_kernel<<<dim3(V_ / 128, E_ / 64, 1), 256>>>(Wh, wh, V_, E_);

    embed_kernel<<<BT_, 256>>>(idx, tok, pos, x);

    for (int l = 0; l < L_; l++) {
        ln_kernel<<<BT_, 256>>>(x, h, l1s + l * E_, l1b + l * E_);

        gemm2(h, wqkv + (long long)l * E_ * QKVW / 2, qk, vt, BT_, QKVW, E_);

        flash_kernel<<<dim3(T_ / 128, B_ * H_), 256, FL_SMEM>>>(qk, vt, oc);

        gemm0(oc, wp + (long long)l * E_ * E_ / 2, x, E_,
              BT_, E_, E_, bp + l * E_, x, 0);

        ln_kernel<<<BT_, 256>>>(x, h, l2s + l * E_, l2b + l * E_);

        gemm1(h, w1 + (long long)l * E_ * FF_ / 2, ff,
              BT_, FF_, E_, b1 + l * FF_);

        gemm0(ff, w2 + (long long)l * FF_ * E_ / 2, x, E_,
              BT_, E_, FF_, b2 + l * E_, x, 0);
    }

    ln_kernel<<<BT_, 256>>>(x, h, lfs, lfb);

    // head GEMM with fused per-warpcol softmax partials
    gemm3(h, wh, out, part, BT_, V_, E_, bh);

    loss_rows_kernel<<<BT_, 256>>>(out, part, tgt, rl);
    if ((long long)out_size >= (long long)BT_ * V_ + 1)
        loss_reduce_kernel<<<1, 1024>>>(rl, out + (long long)BT_ * V_);
}

// round 17
// speedup vs baseline: 1.4856x; 1.0023x over previous
#include <cuda_runtime.h>
#include <cuda_fp16.h>
#include <math.h>
#include <stdint.h>

// Problem config
#define E_   1024
#define H_   16
#define D_   64
#define L_   6
#define FF_  4096
#define B_   4
#define T_   1024
#define BT_  4096
#define V_   32000
#define QKVW 3072
#define NPART 1000           // per-row loss partials: 250 colblocks x 4 warpcols

// Activation scratch
__device__ __align__(16) float    g_x[BT_ * E_];
__device__ __align__(16) uint32_t g_h[BT_ * E_ / 2];
__device__ __align__(16) uint32_t g_qk[BT_ * 1024];
__device__ __align__(16) uint32_t g_vt[B_ * H_ * 64 * T_ / 2];
__device__ __align__(16) uint32_t g_oc[BT_ * E_ / 2];
__device__ __align__(16) uint32_t g_ff[BT_ * FF_ / 2];
__device__ __align__(16) float2   g_part[(size_t)BT_ * NPART];
__device__ __align__(16) float    g_rl[BT_];

// Fragment-packed fp16 weights (tile = 64k x 128n = 4096 b32 words)
__device__ __align__(16) uint32_t g_wqkv[(size_t)L_ * E_ * QKVW / 2];
__device__ __align__(16) uint32_t g_wp[(size_t)L_ * E_ * E_ / 2];
__device__ __align__(16) uint32_t g_w1[(size_t)L_ * E_ * FF_ / 2];
__device__ __align__(16) uint32_t g_w2[(size_t)L_ * FF_ * E_ / 2];
__device__ __align__(16) uint32_t g_wh[(size_t)E_ * V_ / 2];

__device__ __forceinline__ uint32_t h2(float a, float b) {
    __half2 t = __floats2half2_rn(a, b);
    return *(uint32_t*)&t;
}
__device__ __forceinline__ uint32_t hscale(uint32_t u, __half2 s) {
    __half2 t = __hmul2(*(__half2*)&u, s);
    return *(uint32_t*)&t;
}

__device__ __forceinline__ void cpa16(void* s, const void* g) {
    uint32_t sa = (uint32_t)__cvta_generic_to_shared(s);
    asm volatile("cp.async.cg.shared.global [%0], [%1], 16;\n" :: "r"(sa), "l"(g));
}
__device__ __forceinline__ void cpa_commit() { asm volatile("cp.async.commit_group;\n"); }
template<int N> __device__ __forceinline__ void cpa_wait() {
    asm volatile("cp.async.wait_group %0;\n" :: "n"(N));
}

#define MMA_F16(d0,d1,d2,d3,a0,a1,a2,a3,b0,b1) \
    asm volatile("mma.sync.aligned.m16n8k16.row.col.f32.f16.f16.f32 " \
        "{%0,%1,%2,%3}, {%4,%5,%6,%7}, {%8,%9}, {%0,%1,%2,%3};\n" \
        : "+f"(d0), "+f"(d1), "+f"(d2), "+f"(d3) \
        : "r"(a0), "r"(a1), "r"(a2), "r"(a3), "r"(b0), "r"(b1))

// ---------------------------------------------------------------------------
// fp16 GEMM: 128x128 CTA tile, BK=64, 3-stage cp.async (R14 mainloop).
// OMODE 0: fp32 row-major out (+bias/resid/relu)
// OMODE 1: packed-A fp16 out (+bias, relu)
// OMODE 2: qkv split out (Q/K -> Cw rows, V -> (half*)Cf transposed)
// OMODE 3: head: fp32 logits out (+bias) AND per-warpcol partial (max, sumexp)
// ---------------------------------------------------------------------------
#define TSZ 4096
#define G_SMEM (3 * 2 * TSZ * 4)

template<int OMODE>
__global__ __launch_bounds__(256, 2)
void mma_gemm(const uint32_t* __restrict__ Ap,
              const uint32_t* __restrict__ Bp,
              float* __restrict__ Cf,
              uint32_t* __restrict__ Cw,
              float2* __restrict__ part,
              int ldc, int M, int N, int K,
              const float* __restrict__ bias,
              const float* __restrict__ resid,
              int relu)
{
    extern __shared__ __align__(16) uint32_t dsm[];
    uint32_t* Abuf = dsm;
    uint32_t* Bbuf = dsm + 3 * TSZ;

    const int row0 = blockIdx.y * 128;
    const int col0 = blockIdx.x * 128;
    const int tid  = threadIdx.x;
    const int warp = tid >> 5;
    const int lane = tid & 31;
    const int wm   = (warp >> 2) * 64;
    const int wm16 = (warp >> 2) * 4;
    const int wn8  = (warp & 3) * 4;
    const int qr   = lane >> 2;
    const int qc   = lane & 3;

    const int ntn = N >> 7;
    const int nkt = K >> 6;
    const int mt  = row0 >> 7;

    float acc[4][4][4];
#pragma unroll
    for (int i = 0; i < 4; i++)
#pragma unroll
        for (int j = 0; j < 4; j++)
#pragma unroll
            for (int t = 0; t < 4; t++) acc[i][j][t] = 0.f;

    auto issue = [&](int it) {
        int buf = it % 3;
        uint32_t* as = Abuf + buf * TSZ;
        const uint32_t* at = Ap + ((long long)mt * nkt + it) * TSZ;
#pragma unroll
        for (int i = 0; i < 4; i++) {
            int e = tid + i * 256;
            cpa16(&as[e * 4], at + e * 4);
        }
        uint32_t* bs = Bbuf + buf * TSZ;
        const uint32_t* bt = Bp + ((long long)it * ntn + (col0 >> 7)) * TSZ;
#pragma unroll
        for (int i = 0; i < 4; i++) {
            int e = tid + i * 256;
            cpa16(&bs[e * 4], bt + e * 4);
        }
        cpa_commit();
    };

    issue(0);
    issue(1);

    for (int it = 0; it < nkt; it++) {
        if (it + 2 < nkt) issue(it + 2);
        else              cpa_commit();
        cpa_wait<2>();
        __syncthreads();

        const uint32_t* as = Abuf + (it % 3) * TSZ;
        const uint32_t* bs = Bbuf + (it % 3) * TSZ;

#pragma unroll
        for (int kt = 0; kt < 4; kt++) {
            uint4 a[4];
#pragma unroll
            for (int mi = 0; mi < 4; mi++)
                a[mi] = *(const uint4*)&as[((wm16 + mi) * 4 + kt) * 128 + lane * 4];
            uint32_t b[4][2];
#pragma unroll
            for (int ni = 0; ni < 4; ni++) {
                uint2 t2 = *(const uint2*)&bs[((wn8 + ni) * 4 + kt) * 64 + lane * 2];
                b[ni][0] = t2.x; b[ni][1] = t2.y;
            }
#pragma unroll
            for (int mi = 0; mi < 4; mi++)
#pragma unroll
                for (int ni = 0; ni < 4; ni++)
                    MMA_F16(acc[mi][ni][0], acc[mi][ni][1], acc[mi][ni][2], acc[mi][ni][3],
                            a[mi].x, a[mi].y, a[mi].z, a[mi].w,
                            b[ni][0], b[ni][1]);
        }
        __syncthreads();
    }

    if (OMODE == 0) {
#pragma unroll
        for (int mi = 0; mi < 4; mi++) {
#pragma unroll
            for (int ni = 0; ni < 4; ni++) {
#pragma unroll
                for (int half = 0; half < 2; half++) {
                    int r = row0 + wm + mi * 16 + qr + half * 8;
                    int c = col0 + (warp & 3) * 32 + ni * 8 + qc * 2;
                    float v0 = acc[mi][ni][half * 2];
                    float v1 = acc[mi][ni][half * 2 + 1];
                    if (bias) { v0 += bias[c]; v1 += bias[c + 1]; }
                    if (resid) {
                        float2 rr = *(const float2*)(resid + (long long)r * ldc + c);
                        v0 += rr.x; v1 += rr.y;
                    }
                    if (relu) { v0 = fmaxf(v0, 0.f); v1 = fmaxf(v1, 0.f); }
                    *(float2*)(Cf + (long long)r * ldc + c) = make_float2(v0, v1);
                }
            }
        }
    } else if (OMODE == 1) {
        float* stg = (float*)dsm;   // 128 x 130
#pragma unroll
        for (int mi = 0; mi < 4; mi++)
#pragma unroll
            for (int ni = 0; ni < 4; ni++)
#pragma unroll
                for (int half = 0; half < 2; half++) {
                    int r = wm + mi * 16 + qr + half * 8;
                    int c = (warp & 3) * 32 + ni * 8 + qc * 2;
                    *(float2*)&stg[r * 130 + c] =
                        make_float2(acc[mi][ni][half * 2], acc[mi][ni][half * 2 + 1]);
                }
        __syncthreads();
        const int nktC = N >> 6;
#pragma unroll
        for (int i = 0; i < 32; i++) {
            int g  = tid + i * 256;
            int tl = g >> 12;
            int W  = g & 4095;
            int chunk = W >> 9;
            int kt = (W >> 7) & 3;
            int ln = (W >> 2) & 31;
            int w  = W & 3;
            int m  = chunk * 16 + (ln >> 2) + (w & 1) * 8;
            int k  = kt * 16 + (w >> 1) * 8 + (ln & 3) * 2;
            int c  = tl * 64 + k;
            float v0 = stg[m * 130 + c]     + bias[col0 + c];
            float v1 = stg[m * 130 + c + 1] + bias[col0 + c + 1];
            v0 = fmaxf(v0, 0.f); v1 = fmaxf(v1, 0.f);
            Cw[((long long)mt * nktC + (col0 >> 6) + tl) * 4096 + W] = h2(v0, v1);
        }
    } else if (OMODE == 2) {
        __half* vh = (__half*)Cf;
#pragma unroll
        for (int mi = 0; mi < 4; mi++) {
#pragma unroll
            for (int ni = 0; ni < 4; ni++) {
#pragma unroll
                for (int half = 0; half < 2; half++) {
                    int r = row0 + wm + mi * 16 + qr + half * 8;
                    int c = col0 + (warp & 3) * 32 + ni * 8 + qc * 2;
                    float v0 = acc[mi][ni][half * 2];
                    float v1 = acc[mi][ni][half * 2 + 1];
                    int hh = c / 192;
                    int rem = c - hh * 192;
                    int sel = rem >> 6;
                    int d = rem & 63;
                    if (sel < 2) {
                        Cw[(long long)r * 1024 + hh * 64 + sel * 32 + (d >> 1)] = h2(v0, v1);
                    } else {
                        int bb = r >> 10, t = r & 1023;
                        long long base = (long long)((bb * 16 + hh) * 64 + d) * 1024 + t;
                        vh[base]        = __float2half_rn(v0);
                        vh[base + 1024] = __float2half_rn(v1);
                    }
                }
            }
        }
    } else {
        // OMODE 3: logits (+bias) + per-warpcol partial (max, sumexp), no smem
#pragma unroll
        for (int mi = 0; mi < 4; mi++) {
#pragma unroll
            for (int ni = 0; ni < 4; ni++) {
#pragma unroll
                for (int t = 0; t < 4; t++) {
                    int c = col0 + (warp & 3) * 32 + ni * 8 + qc * 2 + (t & 1);
                    acc[mi][ni][t] += bias[c];
                }
#pragma unroll
                for (int half = 0; half < 2; half++) {
                    int r = row0 + wm + mi * 16 + qr + half * 8;
                    int c = col0 + (warp & 3) * 32 + ni * 8 + qc * 2;
                    *(float2*)(Cf + (long long)r * ldc + c) =
                        make_float2(acc[mi][ni][half * 2], acc[mi][ni][half * 2 + 1]);
                }
            }
        }
        const int pcol = (col0 >> 7) * 4 + (warp & 3);
#pragma unroll
        for (int mi = 0; mi < 4; mi++) {
#pragma unroll
            for (int half = 0; half < 2; half++) {
                float m_t = -1e30f;
#pragma unroll
                for (int ni = 0; ni < 4; ni++)
                    m_t = fmaxf(m_t, fmaxf(acc[mi][ni][half * 2], acc[mi][ni][half * 2 + 1]));
                m_t = fmaxf(m_t, __shfl_xor_sync(0xffffffff, m_t, 1));
                m_t = fmaxf(m_t, __shfl_xor_sync(0xffffffff, m_t, 2));
                float s_t = 0.f;
#pragma unroll
                for (int ni = 0; ni < 4; ni++)
                    s_t += __expf(acc[mi][ni][half * 2] - m_t)
                         + __expf(acc[mi][ni][half * 2 + 1] - m_t);
                s_t += __shfl_xor_sync(0xffffffff, s_t, 1);
                s_t += __shfl_xor_sync(0xffffffff, s_t, 2);
                if (qc == 0) {
                    int r = row0 + wm + mi * 16 + qr + half * 8;
                    part[(long long)r * NPART + pcol] = make_float2(m_t, s_t);
                }
            }
        }
    }
}

// ---------------------------------------------------------------------------
// Unified weight packing: single launch; linear block id decoded into
// {qkv, wp, w1, w2, wh} segments. Each CTA packs one 64k x 128n tile.
// ---------------------------------------------------------------------------
#define NB_QKV (24 * 16 * L_)    // 2304
#define NB_WP  (8 * 16 * L_)     // 768
#define NB_W1  (32 * 16 * L_)    // 3072
#define NB_W2  (8 * 64 * L_)     // 3072
#define NB_WH  (250 * 16)        // 4000
#define NB_ALL (NB_QKV + NB_WP + NB_W1 + NB_W2 + NB_WH)

__global__ __launch_bounds__(256)
void pack_all_kernel(const float* __restrict__ Wq, const float* __restrict__ Wk,
                     const float* __restrict__ Wv, const float* __restrict__ Wp,
                     const float* __restrict__ W1, const float* __restrict__ W2,
                     const float* __restrict__ Wh,
                     uint32_t* __restrict__ dqkv, uint32_t* __restrict__ dwp,
                     uint32_t* __restrict__ dw1, uint32_t* __restrict__ dw2,
                     uint32_t* __restrict__ dwh)
{
    __shared__ float sm[64][129];
    const int tid = threadIdx.x;
    int bid = blockIdx.x;

    const float* src = nullptr;      // row-major [K,N] source (generic path)
    uint32_t* dst = nullptr;
    int N = 0, nt = 0, kc = 0;
    bool qkv_mode = false;
    int l = 0;

    if (bid < NB_QKV) {
        qkv_mode = true;
        nt = bid % 24; kc = (bid / 24) % 16; l = bid / (24 * 16);
        dst = dqkv + (long long)l * E_ * QKVW / 2 + ((long long)kc * 24 + nt) * 4096;
    } else if ((bid -= NB_QKV) < NB_WP) {
        nt = bid % 8; kc = (bid / 8) % 16; l = bid / (8 * 16);
        N = E_;
        src = Wp + (long long)l * E_ * E_;
        dst = dwp + (long long)l * E_ * E_ / 2 + ((long long)kc * 8 + nt) * 4096;
    } else if ((bid -= NB_WP) < NB_W1) {
        nt = bid % 32; kc = (bid / 32) % 16; l = bid / (32 * 16);
        N = FF_;
        src = W1 + (long long)l * E_ * FF_;
        dst = dw1 + (long long)l * E_ * FF_ / 2 + ((long long)kc * 32 + nt) * 4096;
    } else if ((bid -= NB_W1) < NB_W2) {
        nt = bid % 8; kc = (bid / 8) % 64; l = bid / (8 * 64);
        N = E_;
        src = W2 + (long long)l * FF_ * E_;
        dst = dw2 + (long long)l * FF_ * E_ / 2 + ((long long)kc * 8 + nt) * 4096;
    } else {
        bid -= NB_W2;
        nt = bid % 250; kc = bid / 250;
        N = V_;
        src = Wh;
        dst = dwh + ((long long)kc * 250 + nt) * 4096;
    }

    if (qkv_mode) {
#pragma unroll
        for (int i = 0; i < 8; i++) {
            int e = tid + i * 256;
            int r = e >> 5, c4 = e & 31;
            int n = nt * 128 + c4 * 4;
            int hh = n / 192;
            int rem = n - hh * 192;
            int sel = rem >> 6;
            int d = rem & 63;
            const float* W = (sel == 0) ? Wq : (sel == 1) ? Wk : Wv;
            float4 f = *(const float4*)(W + (((long long)l * H_ + hh) * E_ + kc * 64 + r) * D_ + d);
            sm[r][c4 * 4 + 0] = f.x; sm[r][c4 * 4 + 1] = f.y;
            sm[r][c4 * 4 + 2] = f.z; sm[r][c4 * 4 + 3] = f.w;
        }
    } else {
#pragma unroll
        for (int i = 0; i < 8; i++) {
            int e = tid + i * 256;
            int r = e >> 5, c4 = e & 31;
            float4 f = *(const float4*)(src + (long long)(kc * 64 + r) * N + nt * 128 + c4 * 4);
            sm[r][c4 * 4 + 0] = f.x; sm[r][c4 * 4 + 1] = f.y;
            sm[r][c4 * 4 + 2] = f.z; sm[r][c4 * 4 + 3] = f.w;
        }
    }
    __syncthreads();
#pragma unroll
    for (int i = 0; i < 16; i++) {
        int W = tid + i * 256;
        int ns = W >> 8;
        int kt = (W >> 6) & 3;
        int rem = W & 63;
        int ln = rem >> 1, w = rem & 1;
        int n = ns * 8 + (ln >> 2);
        int k = kt * 16 + w * 8 + (ln & 3) * 2;
        dst[W] = h2(sm[k][n], sm[k + 1][n]);
    }
}

// ---------------------------------------------------------------------------
// Fused causal flash attention, fp16 mma. Heavy row-blocks scheduled first.
// ---------------------------------------------------------------------------
#define KVW 36
#define KVSZ (64 * KVW)
#define FL_SMEM ((4 * KVSZ + 4096) * 4)

__global__ __launch_bounds__(256, 2)
void flash_kernel(const uint32_t* __restrict__ qk,
                  const uint32_t* __restrict__ vtw,
                  uint32_t* __restrict__ oc)
{
    extern __shared__ __align__(16) uint32_t fsm[];
    uint32_t* Kb = fsm;
    uint32_t* Vb = fsm + 2 * KVSZ;
    uint32_t* Ps = fsm + 4 * KVSZ;

    const int rb   = (int)gridDim.x - 1 - (int)blockIdx.x;   // heavy blocks first
    const int row0 = rb * 128;
    const int b    = blockIdx.y >> 4;
    const int h    = blockIdx.y & 15;
    const int tid  = threadIdx.x;
    const int wid  = tid >> 5;
    const int lane = tid & 31;
    const int qr   = lane >> 2;
    const int qc   = lane & 3;

    const int r1 = row0 + wid * 16 + qr;
    const int bh = b * 16 + h;

    uint32_t aq[4][4];
    {
        const __half2 sc2 = __float2half2_rn(0.03125f);
        const uint32_t* q1 = qk + (long long)(b * T_ + r1) * 1024 + h * 64;
        const uint32_t* q2 = q1 + 8 * 1024;
#pragma unroll
        for (int kt = 0; kt < 4; kt++) {
            aq[kt][0] = hscale(q1[kt * 8 + qc], sc2);
            aq[kt][1] = hscale(q2[kt * 8 + qc], sc2);
            aq[kt][2] = hscale(q1[kt * 8 + qc + 4], sc2);
            aq[kt][3] = hscale(q2[kt * 8 + qc + 4], sc2);
        }
    }

    float o[8][4];
#pragma unroll
    for (int nt = 0; nt < 8; nt++)
#pragma unroll
        for (int t = 0; t < 4; t++) o[nt][t] = 0.f;
    float m0 = -1e30f, m1 = -1e30f, l0 = 0.f, l1 = 0.f;

    const int ntiles = (row0 >> 6) + 2;

    auto issue = [&](int j, int buf) {
        uint32_t* ks = Kb + buf * KVSZ;
        uint32_t* vs = Vb + buf * KVSZ;
#pragma unroll
        for (int i = 0; i < 2; i++) {
            int e = tid + i * 256;
            int kr = e >> 3, qd = e & 7;
            cpa16(&ks[kr * KVW + qd * 4],
                  qk + (long long)(b * T_ + j * 64 + kr) * 1024 + h * 64 + 32 + qd * 4);
        }
#pragma unroll
        for (int i = 0; i < 2; i++) {
            int e = tid + i * 256;
            int dd = e >> 3, qd = e & 7;
            cpa16(&vs[dd * KVW + qd * 4],
                  vtw + (long long)(bh * 64 + dd) * 512 + j * 32 + qd * 4);
        }
        cpa_commit();
    };

    issue(0, 0);
    for (int j = 0; j < ntiles; j++) {
        if (j + 1 < ntiles) { issue(j + 1, (j + 1) & 1); cpa_wait<1>(); }
        else                { cpa_wait<0>(); }
        __syncthreads();

        const uint32_t* ks = Kb + (j & 1) * KVSZ;
        const uint32_t* vs = Vb + (j & 1) * KVSZ;

        float s[8][4];
#pragma unroll
        for (int nt = 0; nt < 8; nt++)
#pragma unroll
            for (int t = 0; t < 4; t++) s[nt][t] = 0.f;
#pragma unroll
        for (int kt = 0; kt < 4; kt++) {
            uint32_t bfr[8][2];
#pragma unroll
            for (int nt = 0; nt < 8; nt++) {
                bfr[nt][0] = ks[(nt * 8 + qr) * KVW + kt * 8 + qc];
                bfr[nt][1] = ks[(nt * 8 + qr) * KVW + kt * 8 + qc + 4];
            }
#pragma unroll
            for (int nt = 0; nt < 8; nt++)
                MMA_F16(s[nt][0], s[nt][1], s[nt][2], s[nt][3],
                        aq[kt][0], aq[kt][1], aq[kt][2], aq[kt][3],
                        bfr[nt][0], bfr[nt][1]);
        }

        const int r2 = r1 + 8;
        if (j * 64 + 63 > row0 + wid * 16) {
#pragma unroll
            for (int nt = 0; nt < 8; nt++) {
                int c = j * 64 + nt * 8 + qc * 2;
                if (c     > r1) s[nt][0] = -1e30f;
                if (c + 1 > r1) s[nt][1] = -1e30f;
                if (c     > r2) s[nt][2] = -1e30f;
                if (c + 1 > r2) s[nt][3] = -1e30f;
            }
        }

        float nm0 = m0, nm1 = m1;
#pragma unroll
        for (int nt = 0; nt < 8; nt++) {
            nm0 = fmaxf(nm0, fmaxf(s[nt][0], s[nt][1]));
            nm1 = fmaxf(nm1, fmaxf(s[nt][2], s[nt][3]));
        }
        nm0 = fmaxf(nm0, __shfl_xor_sync(0xffffffff, nm0, 1));
        nm0 = fmaxf(nm0, __shfl_xor_sync(0xffffffff, nm0, 2));
        nm1 = fmaxf(nm1, __shfl_xor_sync(0xffffffff, nm1, 1));
        nm1 = fmaxf(nm1, __shfl_xor_sync(0xffffffff, nm1, 2));

        float f0 = __expf(m0 - nm0), f1 = __expf(m1 - nm1);
        m0 = nm0; m1 = nm1;

        uint32_t* pw = Ps + wid * 512;
        float rs0 = 0.f, rs1 = 0.f;
        __syncwarp();
#pragma unroll
        for (int nt = 0; nt < 8; nt++) {
            float p0 = __expf(s[nt][0] - nm0);
            float p1 = __expf(s[nt][1] - nm0);
            float p2 = __expf(s[nt][2] - nm1);
            float p3 = __expf(s[nt][3] - nm1);
            rs0 += p0 + p1; rs1 += p2 + p3;
            int base = ((nt >> 1) * 32 + lane) * 4 + 2 * (nt & 1);
            pw[base]     = h2(p0, p1);
            pw[base + 1] = h2(p2, p3);
        }
        rs0 += __shfl_xor_sync(0xffffffff, rs0, 1);
        rs0 += __shfl_xor_sync(0xffffffff, rs0, 2);
        rs1 += __shfl_xor_sync(0xffffffff, rs1, 1);
        rs1 += __shfl_xor_sync(0xffffffff, rs1, 2);
        l0 = l0 * f0 + rs0;
        l1 = l1 * f1 + rs1;

#pragma unroll
        for (int nt = 0; nt < 8; nt++) {
            o[nt][0] *= f0; o[nt][1] *= f0;
            o[nt][2] *= f1; o[nt][3] *= f1;
        }
        __syncwarp();

#pragma unroll
        for (int kt = 0; kt < 4; kt++) {
            uint4 a = *(const uint4*)&pw[(kt * 32 + lane) * 4];
            uint32_t bfr[8][2];
#pragma unroll
            for (int ni = 0; ni < 8; ni++) {
                bfr[ni][0] = vs[(ni * 8 + qr) * KVW + kt * 8 + qc];
                bfr[ni][1] = vs[(ni * 8 + qr) * KVW + kt * 8 + qc + 4];
            }
#pragma unroll
            for (int ni = 0; ni < 8; ni++)
                MMA_F16(o[ni][0], o[ni][1], o[ni][2], o[ni][3],
                        a.x, a.y, a.z, a.w, bfr[ni][0], bfr[ni][1]);
        }
        __syncthreads();
    }

    float i0 = 1.f / l0, i1 = 1.f / l1;
    long long tb = ((long long)((b * 8 + rb) * 16 + h)) * 4096;
    int base = wid * 512 + (qr * 4 + qc) * 4;
#pragma unroll
    for (int nt = 0; nt < 8; nt++) {
        long long off = tb + base + (nt >> 1) * 128 + 2 * (nt & 1);
        oc[off]     = h2(o[nt][0] * i0, o[nt][1] * i0);
        oc[off + 1] = h2(o[nt][2] * i1, o[nt][3] * i1);
    }
}

// ---------------------------------------------------------------------------
__global__ void embed_kernel(const int* __restrict__ idx,
                             const float* __restrict__ tok,
                             const float* __restrict__ pos,
                             float* __restrict__ x)
{
    int row = blockIdx.x;
    int t   = row & (T_ - 1);
    int tk  = idx[row];
    const float* te = tok + (long long)tk * E_;
    const float* pe = pos + (long long)t  * E_;
    float* xr = x + (long long)row * E_;
    for (int c = threadIdx.x; c < E_; c += blockDim.x)
        xr[c] = te[c] + pe[c];
}

__global__ void ln_kernel(const float* __restrict__ x, uint32_t* __restrict__ yp,
                          const float* __restrict__ sc, const float* __restrict__ bi)
{
    int row = blockIdx.x;
    int tid = threadIdx.x;
    float4 f = ((const float4*)(x + (long long)row * E_))[tid];
    float sum = f.x + f.y + f.z + f.w;
    float sq  = f.x * f.x + f.y * f.y + f.z * f.z + f.w * f.w;
    __shared__ float s1[256], s2[256];
    s1[tid] = sum; s2[tid] = sq;
    __syncthreads();
    for (int st = 128; st > 0; st >>= 1) {
        if (tid < st) { s1[tid] += s1[tid + st]; s2[tid] += s2[tid + st]; }
        __syncthreads();
    }
    float mean = s1[0] * (1.f / E_);
    float var  = s2[0] * (1.f / E_) - mean * mean;
    float inv  = rsqrtf(var + 1e-5f);

    int c = tid * 4;
    float y0 = (f.x - mean) * inv * sc[c]     + bi[c];
    float y1 = (f.y - mean) * inv * sc[c + 1] + bi[c + 1];
    float y2 = (f.z - mean) * inv * sc[c + 2] + bi[c + 2];
    float y3 = (f.w - mean) * inv * sc[c + 3] + bi[c + 3];

    int kk = c & 63;
    long long tb = ((long long)(row >> 7) * 16 + (c >> 6)) * 4096;
    int base = (((row & 127) >> 4) * 4 + (kk >> 4)) * 128
             + ((row & 7) * 4 + ((kk & 7) >> 1)) * 4
             + ((row >> 3) & 1) + 2 * ((kk >> 3) & 1);
    yp[tb + base]     = h2(y0, y1);
    yp[tb + base + 4] = h2(y2, y3);
}

// Merge NPART per-(block,warpcol) partials per row -> weighted CE
__global__ void loss_rows_kernel(const float* __restrict__ logits,
                                 const float2* __restrict__ part,
                                 const int* __restrict__ tgt,
                                 float* __restrict__ rl)
{
    int row = blockIdx.x;
    int tid = threadIdx.x;
    float m = -1e30f, s = 0.f;
    const float2* pr = part + (long long)row * NPART;
    for (int i = tid; i < NPART; i += 256) {
        float2 p = pr[i];
        float nm = fmaxf(m, p.x);
        s = s * __expf(m - nm) + p.y * __expf(p.x - nm);
        m = nm;
    }
    __shared__ float sm[256], ss[256];
    sm[tid] = m; ss[tid] = s;
    __syncthreads();
    for (int st = 128; st > 0; st >>= 1) {
        if (tid < st) {
            float m2 = sm[tid + st], s2 = ss[tid + st];
            float nm = fmaxf(sm[tid], m2);
            ss[tid] = ss[tid] * __expf(sm[tid] - nm) + s2 * __expf(m2 - nm);
            sm[tid] = nm;
        }
        __syncthreads();
    }
    if (tid == 0) {
        float lse = sm[0] + __logf(ss[0]);
        int t = tgt[row];
        float ce = lse - logits[(long long)row * V_ + t];
        float w = 1.f;
        if (t == 4 || t == 3 || t == 1) w = 1.5f;
        if (t == 2) w = 2.0f;
        if (t == 0) w = 0.1f;
        rl[row] = ce * w;
    }
}

__global__ void loss_reduce_kernel(const float* __restrict__ rl, float* __restrict__ out)
{
    __shared__ float sm[1024];
    float s = 0.f;
    for (int i = threadIdx.x; i < BT_; i += 1024) s += rl[i];
    sm[threadIdx.x] = s;
    __syncthreads();
    for (int st = 512; st > 0; st >>= 1) {
        if (threadIdx.x < st) sm[threadIdx.x] += sm[threadIdx.x + st];
        __syncthreads();
    }
    if (threadIdx.x == 0) *out = sm[0] * (1.f / BT_);
}

// ---------------------------------------------------------------------------
static inline void gemm0(const uint32_t* A, const uint32_t* Bp,
                         float* Cf, int ldc, int M, int N, int K,
                         const float* bias, const float* resid, int relu)
{
    dim3 grid(N / 128, M / 128, 1);
    mma_gemm<0><<<grid, 256, G_SMEM>>>(A, Bp, Cf, nullptr, nullptr, ldc, M, N, K,
                                       bias, resid, relu);
}

static inline void gemm1(const uint32_t* A, const uint32_t* Bp,
                         uint32_t* Cw, int M, int N, int K, const float* bias)
{
    dim3 grid(N / 128, M / 128, 1);
    mma_gemm<1><<<grid, 256, G_SMEM>>>(A, Bp, nullptr, Cw, nullptr, 0, M, N, K,
                                       bias, nullptr, 1);
}

static inline void gemm2(const uint32_t* A, const uint32_t* Bp,
                         uint32_t* qk, uint32_t* vt, int M, int N, int K)
{
    dim3 grid(N / 128, M / 128, 1);
    mma_gemm<2><<<grid, 256, G_SMEM>>>(A, Bp, (float*)vt, qk, nullptr, 0, M, N, K,
                                       nullptr, nullptr, 0);
}

static inline void gemm3(const uint32_t* A, const uint32_t* Bp,
                         float* Cf, float2* part, int M, int N, int K,
                         const float* bias)
{
    dim3 grid(N / 128, M / 128, 1);
    mma_gemm<3><<<grid, 256, G_SMEM>>>(A, Bp, Cf, nullptr, part, N, M, N, K,
                                       bias, nullptr, 0);
}

extern "C" void kernel_launch(void* const* d_in, const int* in_sizes, int n_in,
                              void* d_out, int out_size)
{
    const int*   idx = (const int*)d_in[0];
    const int*   tgt = (const int*)d_in[1];
    const float* tok = (const float*)d_in[2];
    const float* pos = (const float*)d_in[3];
    const float* Wq  = (const float*)d_in[4];
    const float* Wk  = (const float*)d_in[5];
    const float* Wv  = (const float*)d_in[6];
    const float* Wp  = (const float*)d_in[7];
    const float* bp  = (const float*)d_in[8];
    const float* W1  = (const float*)d_in[9];
    const float* b1  = (const float*)d_in[10];
    const float* W2  = (const float*)d_in[11];
    const float* b2  = (const float*)d_in[12];
    const float* l1s = (const float*)d_in[13];
    const float* l1b = (const float*)d_in[14];
    const float* l2s = (const float*)d_in[15];
    const float* l2b = (const float*)d_in[16];
    const float* lfs = (const float*)d_in[17];
    const float* lfb = (const float*)d_in[18];
    const float* Wh  = (const float*)d_in[19];
    const float* bh  = (const float*)d_in[20];
    float* out = (float*)d_out;

    cudaFuncSetAttribute(mma_gemm<0>, cudaFuncAttributeMaxDynamicSharedMemorySize, G_SMEM);
    cudaFuncSetAttribute(mma_gemm<1>, cudaFuncAttributeMaxDynamicSharedMemorySize, G_SMEM);
    cudaFuncSetAttribute(mma_gemm<2>, cudaFuncAttributeMaxDynamicSharedMemorySize, G_SMEM);
    cudaFuncSetAttribute(mma_gemm<3>, cudaFuncAttributeMaxDynamicSharedMemorySize, G_SMEM);
    cudaFuncSetAttribute(flash_kernel, cudaFuncAttributeMaxDynamicSharedMemorySize, FL_SMEM);

    float *x, *rl;
    float2* part;
    uint32_t *h, *qk, *vt, *oc, *ff;
    uint32_t *wqkv, *wp, *w1, *w2, *wh;
    cudaGetSymbolAddress((void**)&x,    g_x);
    cudaGetSymbolAddress((void**)&h,    g_h);
    cudaGetSymbolAddress((void**)&qk,   g_qk);
    cudaGetSymbolAddress((void**)&vt,   g_vt);
    cudaGetSymbolAddress((void**)&oc,   g_oc);
    cudaGetSymbolAddress((void**)&ff,   g_ff);
    cudaGetSymbolAddress((void**)&part, g_part);
    cudaGetSymbolAddress((void**)&rl,   g_rl);
    cudaGetSymbolAddress((void**)&wqkv, g_wqkv);
    cudaGetSymbolAddress((void**)&wp,   g_wp);
    cudaGetSymbolAddress((void**)&w1,   g_w1);
    cudaGetSymbolAddress((void**)&w2,   g_w2);
    cudaGetSymbolAddress((void**)&wh,   g_wh);

    // Weight prep: one merged launch
    pack_all_kernel<<<NB_ALL, 256>>>(Wq, Wk, Wv, Wp, W1, W2, Wh,
                                     wqkv, wp, w1, w2, wh);

    embed_kernel<<<BT_, 256>>>(idx, tok, pos, x);

    for (int l = 0; l < L_; l++) {
        ln_kernel<<<BT_, 256>>>(x, h, l1s + l * E_, l1b + l * E_);

        gemm2(h, wqkv + (long long)l * E_ * QKVW / 2, qk, vt, BT_, QKVW, E_);

        flash_kernel<<<dim3(T_ / 128, B_ * H_), 256, FL_SMEM>>>(qk, vt, oc);

        gemm0(oc, wp + (long long)l * E_ * E_ / 2, x, E_,
              BT_, E_, E_, bp + l * E_, x, 0);

        ln_kernel<<<BT_, 256>>>(x, h, l2s + l * E_, l2b + l * E_);

        gemm1(h, w1 + (long long)l * E_ * FF_ / 2, ff,
              BT_, FF_, E_, b1 + l * FF_);

        gemm0(ff, w2 + (long long)l * FF_ * E_ / 2, x, E_,
              BT_, E_, FF_, b2 + l * E_, x, 0);
    }

    ln_kernel<<<BT_, 256>>>(x, h, lfs, lfb);

    // head GEMM with fused per-warpcol softmax partials
    gemm3(h, wh, out, part, BT_, V_, E_, bh);

    loss_rows_kernel<<<BT_, 256>>>(out, part, tgt, rl);
    if ((long long)out_size >= (long long)BT_ * V_ + 1)
        loss_reduce_kernel<<<1, 1024>>>(rl, out + (long long)BT_ * V_);
}